// round 1
// baseline (speedup 1.0000x reference)
#include <cuda_runtime.h>

#define T_SEQ 2048
#define DIM 4096
#define KV_DIM 1024
#define NH 32
#define NKV 8
#define HD 128

// Scratch (allocation-free rule: __device__ globals)
__device__ float g_q[T_SEQ * DIM];     // 32 MB
__device__ float g_k[T_SEQ * KV_DIM];  //  8 MB
__device__ float g_v[T_SEQ * KV_DIM];  //  8 MB
__device__ float g_y[T_SEQ * DIM];     // 32 MB

// ---------------------------------------------------------------------------
// C[T x N] = A[T x K] * W[N x K]^T   (both row-major, K contiguous)
// 64x64 block, BK=16, 256 threads, 4x4 per thread, smem-tiled w/ prefetch.
// All dims here are multiples of 64/16 so no bounds checks.
// ---------------------------------------------------------------------------
__global__ __launch_bounds__(256) void gemm_nt(const float* __restrict__ A,
                                               const float* __restrict__ W,
                                               float* __restrict__ C,
                                               int N, int K) {
    __shared__ float As[16][68];   // pad 4 keeps float4 alignment + kills conflicts
    __shared__ float Ws[16][68];

    const int tx = (threadIdx.x & 15) << 2;   // 0..60  (n within tile)
    const int ty = (threadIdx.x >> 4) << 2;   // 0..60  (m within tile)
    const int lr = threadIdx.x >> 2;          // 0..63  loader row
    const int lc = (threadIdx.x & 3) << 2;    // 0,4,8,12 loader k-offset

    const float* Ag = A + (size_t)(blockIdx.y * 64 + lr) * K + lc;
    const float* Wg = W + (size_t)(blockIdx.x * 64 + lr) * K + lc;

    float acc[4][4] = {};

    float4 av = *(const float4*)Ag;
    float4 wv = *(const float4*)Wg;

    for (int k0 = 0; k0 < K; k0 += 16) {
        As[lc + 0][lr] = av.x; As[lc + 1][lr] = av.y;
        As[lc + 2][lr] = av.z; As[lc + 3][lr] = av.w;
        Ws[lc + 0][lr] = wv.x; Ws[lc + 1][lr] = wv.y;
        Ws[lc + 2][lr] = wv.z; Ws[lc + 3][lr] = wv.w;
        __syncthreads();

        if (k0 + 16 < K) {   // prefetch next tile while computing
            av = *(const float4*)(Ag + k0 + 16);
            wv = *(const float4*)(Wg + k0 + 16);
        }

        #pragma unroll
        for (int kk = 0; kk < 16; kk++) {
            float a[4], b[4];
            *(float4*)a = *(const float4*)&As[kk][ty];
            *(float4*)b = *(const float4*)&Ws[kk][tx];
            #pragma unroll
            for (int i = 0; i < 4; i++)
                #pragma unroll
                for (int j = 0; j < 4; j++)
                    acc[i][j] = fmaf(a[i], b[j], acc[i][j]);
        }
        __syncthreads();
    }

    const int row0 = blockIdx.y * 64 + ty;
    const int col0 = blockIdx.x * 64 + tx;
    #pragma unroll
    for (int i = 0; i < 4; i++) {
        float4 o = make_float4(acc[i][0], acc[i][1], acc[i][2], acc[i][3]);
        *(float4*)&C[(size_t)(row0 + i) * N + col0] = o;
    }
}

// ---------------------------------------------------------------------------
// RoPE on q (32 heads) and k (8 heads), in place. One thread per (t, head, d<64).
// ---------------------------------------------------------------------------
__global__ __launch_bounds__(256) void rope_kernel(float* __restrict__ q,
                                                   float* __restrict__ k,
                                                   const float* __restrict__ cs,
                                                   const float* __restrict__ sn,
                                                   const int* __restrict__ spp) {
    int idx = blockIdx.x * 256 + threadIdx.x;
    const int total = T_SEQ * (NH + NKV) * (HD / 2);
    if (idx >= total) return;
    int d = idx & 63;
    int h = (idx >> 6) % (NH + NKV);
    int t = idx / (64 * (NH + NKV));
    int sp = *spp;
    float c = cs[(size_t)(sp + t) * 64 + d];
    float s = sn[(size_t)(sp + t) * 64 + d];
    float* p = (h < NH) ? (q + (size_t)t * DIM + h * HD)
                        : (k + (size_t)t * KV_DIM + (h - NH) * HD);
    float x1 = p[d], x2 = p[d + 64];
    p[d]      = x1 * c - x2 * s;
    p[d + 64] = x2 * c + x1 * s;
}

// ---------------------------------------------------------------------------
// Causal flash attention, fp32.
// Block = (q-tile of 64 rows, head). 256 threads = 8 warps, 8 q-rows per warp.
// q tile staged (pre-scaled) in smem; K tile (32 x 128) staged in smem with an
// XOR swizzle so phase-1 reads (lane <-> key) are conflict-free; V read
// directly from global (perfectly coalesced, L1-served across the 8 warps).
// Static smem = 32 KB (q) + 16 KB (k) = exactly 48 KB.
// ---------------------------------------------------------------------------
__global__ __launch_bounds__(256) void attn_kernel(const float* __restrict__ q,
                                                   const float* __restrict__ k,
                                                   const float* __restrict__ v,
                                                   float* __restrict__ y) {
    __shared__ float qS[64 * 128];
    __shared__ float kS[32 * 128];

    const int qt   = blockIdx.x;   // 0..31
    const int h    = blockIdx.y;   // 0..31
    const int kvh  = h >> 2;
    const int tid  = threadIdx.x;
    const int warp = tid >> 5;
    const int lane = tid & 31;
    const float scale = 0.08838834764831845f;  // 1/sqrt(128)

    // Load + pre-scale q tile (64 x 128)
    for (int i = tid; i < 64 * 32; i += 256) {
        int r = i >> 5;
        int c = (i & 31) << 2;
        float4 qv = *(const float4*)&q[(size_t)(qt * 64 + r) * DIM + h * HD + c];
        qv.x *= scale; qv.y *= scale; qv.z *= scale; qv.w *= scale;
        *(float4*)&qS[r * 128 + c] = qv;
    }

    float  m[8], l[8];
    float4 acc[8];
    #pragma unroll
    for (int r = 0; r < 8; r++) {
        m[r] = -1e30f; l[r] = 0.f; acc[r] = make_float4(0.f, 0.f, 0.f, 0.f);
    }

    const int row0   = qt * 64 + warp * 8;   // warp's first global q row
    const int ntiles = qt * 2 + 2;           // key tiles of 32 covering causal span

    for (int kt = 0; kt < ntiles; kt++) {
        const int kbase = kt * 32;
        __syncthreads();                     // protect kS from previous iter readers
        // Load K tile: row j, logical 16B-chunk c stored at chunk (c ^ j)
        for (int i = tid; i < 32 * 32; i += 256) {
            int j = i >> 5;
            int c = i & 31;
            float4 kv = *(const float4*)&k[(size_t)(kbase + j) * KV_DIM + kvh * HD + c * 4];
            *(float4*)&kS[j * 128 + ((c ^ j) & 31) * 4] = kv;
        }
        __syncthreads();

        if (kbase <= row0 + 7) {             // warp has live rows in this tile
            // Phase 1: lane <-> key. S[r] = q_row(r) . k_key(lane)
            float S[8] = {0.f, 0.f, 0.f, 0.f, 0.f, 0.f, 0.f, 0.f};
            const int j = lane;
            #pragma unroll 4
            for (int ci = 0; ci < 32; ci++) {
                float4 kv = *(const float4*)&kS[j * 128 + ((ci ^ j) & 31) * 4];
                #pragma unroll
                for (int r = 0; r < 8; r++) {
                    float4 qv = *(const float4*)&qS[(warp * 8 + r) * 128 + ci * 4];
                    S[r] = fmaf(qv.x, kv.x, S[r]);
                    S[r] = fmaf(qv.y, kv.y, S[r]);
                    S[r] = fmaf(qv.z, kv.z, S[r]);
                    S[r] = fmaf(qv.w, kv.w, S[r]);
                }
            }

            // Phase 2: online softmax (per row, warp-wide over the 32 keys)
            float P[8];
            const int kj = kbase + lane;
            #pragma unroll
            for (int r = 0; r < 8; r++) {
                const int rg = row0 + r;
                float s = (kj <= rg) ? S[r] : -1e30f;
                float tm = s;
                #pragma unroll
                for (int o = 16; o > 0; o >>= 1)
                    tm = fmaxf(tm, __shfl_xor_sync(0xffffffffu, tm, o));
                float mn = fmaxf(m[r], tm);
                float sc = __expf(m[r] - mn);
                float p  = __expf(s - mn);     // masked lanes -> exp(-huge) = 0
                float ts = p;
                #pragma unroll
                for (int o = 16; o > 0; o >>= 1)
                    ts += __shfl_xor_sync(0xffffffffu, ts, o);
                l[r] = l[r] * sc + ts;
                m[r] = mn;
                acc[r].x *= sc; acc[r].y *= sc; acc[r].z *= sc; acc[r].w *= sc;
                P[r] = p;
            }

            // Phase 3: acc += P * V, V streamed from global (coalesced, L1-hot)
            const float* vbase = v + (size_t)kbase * KV_DIM + kvh * HD + lane * 4;
            #pragma unroll 4
            for (int jj = 0; jj < 32; jj++) {
                float4 vv = *(const float4*)(vbase + (size_t)jj * KV_DIM);
                #pragma unroll
                for (int r = 0; r < 8; r++) {
                    float pj = __shfl_sync(0xffffffffu, P[r], jj);
                    acc[r].x = fmaf(pj, vv.x, acc[r].x);
                    acc[r].y = fmaf(pj, vv.y, acc[r].y);
                    acc[r].z = fmaf(pj, vv.z, acc[r].z);
                    acc[r].w = fmaf(pj, vv.w, acc[r].w);
                }
            }
        }
    }

    // Epilogue
    #pragma unroll
    for (int r = 0; r < 8; r++) {
        float inv = 1.0f / l[r];
        float4 o = acc[r];
        o.x *= inv; o.y *= inv; o.z *= inv; o.w *= inv;
        *(float4*)&y[(size_t)(row0 + r) * DIM + h * HD + lane * 4] = o;
    }
}

// ---------------------------------------------------------------------------
// kernel_launch: 6 launches, all graph-capturable, no allocations.
// Input order (metadata): x, cos, sin, wq, wk, wv, wo, start_pos
// ---------------------------------------------------------------------------
extern "C" void kernel_launch(void* const* d_in, const int* in_sizes, int n_in,
                              void* d_out, int out_size) {
    const float* x  = (const float*)d_in[0];
    const float* cs = (const float*)d_in[1];
    const float* sn = (const float*)d_in[2];
    const float* wq = (const float*)d_in[3];
    const float* wk = (const float*)d_in[4];
    const float* wv = (const float*)d_in[5];
    const float* wo = (const float*)d_in[6];
    const int*   sp = (const int*)d_in[7];
    float* out = (float*)d_out;

    float *q, *k, *v, *y;
    cudaGetSymbolAddress((void**)&q, g_q);
    cudaGetSymbolAddress((void**)&k, g_k);
    cudaGetSymbolAddress((void**)&v, g_v);
    cudaGetSymbolAddress((void**)&y, g_y);

    dim3 blk(256);
    // Projections
    gemm_nt<<<dim3(DIM / 64,    T_SEQ / 64), blk>>>(x, wq, q, DIM,    DIM);
    gemm_nt<<<dim3(KV_DIM / 64, T_SEQ / 64), blk>>>(x, wk, k, KV_DIM, DIM);
    gemm_nt<<<dim3(KV_DIM / 64, T_SEQ / 64), blk>>>(x, wv, v, KV_DIM, DIM);
    // RoPE (q + k)
    rope_kernel<<<(T_SEQ * (NH + NKV) * (HD / 2) + 255) / 256, blk>>>(q, k, cs, sn, sp);
    // Causal GQA flash attention
    attn_kernel<<<dim3(T_SEQ / 64, NH), blk>>>(q, k, v, y);
    // Output projection
    gemm_nt<<<dim3(DIM / 64, T_SEQ / 64), blk>>>(y, wo, out, DIM, DIM);
}

// round 3
// speedup vs baseline: 1.9616x; 1.9616x over previous
#include <cuda_runtime.h>
#include <cuda_bf16.h>
#include <cstdint>

#define T_SEQ 2048
#define DIM 4096
#define KV_DIM 1024
#define NH 32
#define NKV 8
#define HD 128

// ---------------- scratch (__device__ globals; allocation-free rule) --------
__device__ float g_q[T_SEQ * DIM];
__device__ float g_k[T_SEQ * KV_DIM];
__device__ float g_v[T_SEQ * KV_DIM];
__device__ float g_y[T_SEQ * DIM];

__device__ __align__(16) __nv_bfloat16 g_xh[T_SEQ * DIM];
__device__ __align__(16) __nv_bfloat16 g_xl[T_SEQ * DIM];
__device__ __align__(16) __nv_bfloat16 g_yh[T_SEQ * DIM];
__device__ __align__(16) __nv_bfloat16 g_yl[T_SEQ * DIM];
__device__ __align__(16) __nv_bfloat16 g_wqh[DIM * DIM];
__device__ __align__(16) __nv_bfloat16 g_wql[DIM * DIM];
__device__ __align__(16) __nv_bfloat16 g_wkh[KV_DIM * DIM];
__device__ __align__(16) __nv_bfloat16 g_wkl[KV_DIM * DIM];
__device__ __align__(16) __nv_bfloat16 g_wvh[KV_DIM * DIM];
__device__ __align__(16) __nv_bfloat16 g_wvl[KV_DIM * DIM];
__device__ __align__(16) __nv_bfloat16 g_woh[DIM * DIM];
__device__ __align__(16) __nv_bfloat16 g_wol[DIM * DIM];

// ---------------- portable PTX helpers (sm_80+ features only) ---------------
__device__ __forceinline__ uint32_t smem_u32(const void* p) {
    uint32_t a;
    asm("{ .reg .u64 t; cvta.to.shared.u64 t, %1; cvt.u32.u64 %0, t; }" : "=r"(a) : "l"(p));
    return a;
}
#define CP_ASYNC16(dst, src) \
    asm volatile("cp.async.cg.shared.global [%0], [%1], 16;" :: "r"(dst), "l"(src) : "memory")
#define CP_COMMIT() asm volatile("cp.async.commit_group;" ::: "memory")
#define CP_WAIT1()  asm volatile("cp.async.wait_group 1;" ::: "memory")
#define LDS32(v, addr) asm volatile("ld.shared.b32 %0, [%1];" : "=r"(v) : "r"(addr))

__device__ __forceinline__ void mma16816(float* c, const uint32_t* a, const uint32_t* b) {
    asm volatile(
        "mma.sync.aligned.m16n8k16.row.col.f32.bf16.bf16.f32 "
        "{%0,%1,%2,%3}, {%4,%5,%6,%7}, {%8,%9}, {%0,%1,%2,%3};"
        : "+f"(c[0]), "+f"(c[1]), "+f"(c[2]), "+f"(c[3])
        : "r"(a[0]), "r"(a[1]), "r"(a[2]), "r"(a[3]), "r"(b[0]), "r"(b[1]));
}

// ---------------------------------------------------------------------------
// fp32 -> (bf16 hi, bf16 lo) split converter
// ---------------------------------------------------------------------------
__global__ __launch_bounds__(256) void cvt_hilo(const float* __restrict__ x,
                                                __nv_bfloat16* __restrict__ h,
                                                __nv_bfloat16* __restrict__ l, int n4) {
    int i = blockIdx.x * 256 + threadIdx.x;
    if (i >= n4) return;
    float4 v = ((const float4*)x)[i];
    __nv_bfloat16 h0 = __float2bfloat16(v.x), h1 = __float2bfloat16(v.y);
    __nv_bfloat16 h2 = __float2bfloat16(v.z), h3 = __float2bfloat16(v.w);
    __nv_bfloat16 l0 = __float2bfloat16(v.x - __bfloat162float(h0));
    __nv_bfloat16 l1 = __float2bfloat16(v.y - __bfloat162float(h1));
    __nv_bfloat16 l2 = __float2bfloat16(v.z - __bfloat162float(h2));
    __nv_bfloat16 l3 = __float2bfloat16(v.w - __bfloat162float(h3));
    ((__nv_bfloat162*)h)[2 * i]     = __nv_bfloat162(h0, h1);
    ((__nv_bfloat162*)h)[2 * i + 1] = __nv_bfloat162(h2, h3);
    ((__nv_bfloat162*)l)[2 * i]     = __nv_bfloat162(l0, l1);
    ((__nv_bfloat162*)l)[2 * i + 1] = __nv_bfloat162(l2, l3);
}

// ---------------------------------------------------------------------------
// mma.sync bf16 hi/lo GEMM: C[M x N] = A[M x K] * W[N x K]^T  (fp32 out)
// CTA tile 128x128, BK=32, 4 warps (warp tile 64x64), cp.async double buffer.
// Smem per stage: 4 tiles (Ah,Al,Bh,Bl), 128 rows x 32 bf16, row padded to 40.
// Fragment LDS is conflict-free: bank(m,k) = (20m + k/2) mod 32 is a bijection.
// ---------------------------------------------------------------------------
#define ROWP 80                 // 40 bf16 row pitch (bytes)
#define TILEB (128 * ROWP)      // 10240 B per tile
#define STAGEB (4 * TILEB)      // 40960 B per stage
#define GEMM_SMEM (2 * STAGEB)  // 81920 B

__global__ __launch_bounds__(128, 2) void gemm_mma(
    const __nv_bfloat16* __restrict__ Ah, const __nv_bfloat16* __restrict__ Al,
    const __nv_bfloat16* __restrict__ Bh, const __nv_bfloat16* __restrict__ Bl,
    float* __restrict__ C, int N, int K) {
    extern __shared__ char smem[];
    const uint32_t sb = smem_u32(smem);
    const int tid = threadIdx.x, warp = tid >> 5, lane = tid & 31;
    const int wm = (warp >> 1) * 64, wn = (warp & 1) * 64;
    const int m0 = blockIdx.y << 7, n0 = blockIdx.x << 7;
    const int NC = K >> 5;

    float acc[4][8][4];
    #pragma unroll
    for (int mt = 0; mt < 4; mt++)
        #pragma unroll
        for (int nt = 0; nt < 8; nt++)
            #pragma unroll
            for (int j = 0; j < 4; j++) acc[mt][nt][j] = 0.f;

    auto load_stage = [&](int kofs, int s) {
        const uint32_t base = sb + s * STAGEB;
        #pragma unroll
        for (int t = 0; t < 4; t++) {
            const __nv_bfloat16* src = (t == 0) ? Ah : (t == 1) ? Al : (t == 2) ? Bh : Bl;
            const int rb = (t < 2) ? m0 : n0;
            #pragma unroll
            for (int i = 0; i < 4; i++) {
                int idx = tid + (i << 7);
                int r = idx >> 2, c = idx & 3;
                uint32_t d = base + t * TILEB + r * ROWP + (c << 4);
                const void* g = src + (size_t)(rb + r) * K + kofs + (c << 3);
                CP_ASYNC16(d, g);
            }
        }
    };

    load_stage(0, 0);
    CP_COMMIT();
    if (NC > 1) load_stage(32, 1);
    CP_COMMIT();

    const int g4 = lane >> 2;              // 0..7
    const int t4 = lane & 3;               // 0..3

    for (int c = 0; c < NC; c++) {
        const int s = c & 1;
        CP_WAIT1();
        __syncthreads();
        const uint32_t st = sb + s * STAGEB;

        #pragma unroll
        for (int ks = 0; ks < 2; ks++) {
            const uint32_t kb = ((ks << 4) + (t4 << 1)) << 1;   // byte offset of k
            uint32_t ah[4][4], al[4][4];
            #pragma unroll
            for (int mt = 0; mt < 4; mt++) {
                uint32_t r0 = st + (wm + (mt << 4) + g4) * ROWP + kb;
                LDS32(ah[mt][0], r0);            LDS32(ah[mt][1], r0 + 8 * ROWP);
                LDS32(ah[mt][2], r0 + 16);       LDS32(ah[mt][3], r0 + 8 * ROWP + 16);
                uint32_t r1 = r0 + TILEB;
                LDS32(al[mt][0], r1);            LDS32(al[mt][1], r1 + 8 * ROWP);
                LDS32(al[mt][2], r1 + 16);       LDS32(al[mt][3], r1 + 8 * ROWP + 16);
            }
            #pragma unroll
            for (int nt = 0; nt < 8; nt++) {
                uint32_t rb0 = st + 2 * TILEB + (wn + (nt << 3) + g4) * ROWP + kb;
                uint32_t bh[2], bl[2];
                LDS32(bh[0], rb0);               LDS32(bh[1], rb0 + 16);
                LDS32(bl[0], rb0 + TILEB);       LDS32(bl[1], rb0 + TILEB + 16);
                #pragma unroll
                for (int mt = 0; mt < 4; mt++) {
                    mma16816(acc[mt][nt], ah[mt], bh);
                    mma16816(acc[mt][nt], al[mt], bh);
                    mma16816(acc[mt][nt], ah[mt], bl);
                }
            }
        }
        __syncthreads();
        if (c + 2 < NC) load_stage((c + 2) << 5, s);
        CP_COMMIT();
    }

    // epilogue: c0,c1 -> (row, 2t..2t+1), c2,c3 -> (row+8, ...)
    #pragma unroll
    for (int mt = 0; mt < 4; mt++) {
        const int row = m0 + wm + (mt << 4) + g4;
        #pragma unroll
        for (int nt = 0; nt < 8; nt++) {
            const int col = n0 + wn + (nt << 3) + (t4 << 1);
            *(float2*)&C[(size_t)row * N + col]       = make_float2(acc[mt][nt][0], acc[mt][nt][1]);
            *(float2*)&C[(size_t)(row + 8) * N + col] = make_float2(acc[mt][nt][2], acc[mt][nt][3]);
        }
    }
}

// ---------------------------------------------------------------------------
// RoPE (unchanged)
// ---------------------------------------------------------------------------
__global__ __launch_bounds__(256) void rope_kernel(float* __restrict__ q,
                                                   float* __restrict__ k,
                                                   const float* __restrict__ cs,
                                                   const float* __restrict__ sn,
                                                   const int* __restrict__ spp) {
    int idx = blockIdx.x * 256 + threadIdx.x;
    const int total = T_SEQ * (NH + NKV) * (HD / 2);
    if (idx >= total) return;
    int d = idx & 63;
    int h = (idx >> 6) % (NH + NKV);
    int t = idx / (64 * (NH + NKV));
    int sp = *spp;
    float c = cs[(size_t)(sp + t) * 64 + d];
    float s = sn[(size_t)(sp + t) * 64 + d];
    float* p = (h < NH) ? (q + (size_t)t * DIM + h * HD)
                        : (k + (size_t)t * KV_DIM + (h - NH) * HD);
    float x1 = p[d], x2 = p[d + 64];
    p[d]      = x1 * c - x2 * s;
    p[d + 64] = x2 * c + x1 * s;
}

// ---------------------------------------------------------------------------
// Causal GQA flash attention, fp32 (unchanged — proven in round 1)
// ---------------------------------------------------------------------------
__global__ __launch_bounds__(256) void attn_kernel(const float* __restrict__ q,
                                                   const float* __restrict__ k,
                                                   const float* __restrict__ v,
                                                   float* __restrict__ y) {
    __shared__ float qS[64 * 128];
    __shared__ float kS[32 * 128];

    const int qt = blockIdx.x;
    const int h = blockIdx.y;
    const int kvh = h >> 2;
    const int tid = threadIdx.x;
    const int warp = tid >> 5;
    const int lane = tid & 31;
    const float scale = 0.08838834764831845f;

    for (int i = tid; i < 64 * 32; i += 256) {
        int r = i >> 5;
        int c = (i & 31) << 2;
        float4 qv = *(const float4*)&q[(size_t)(qt * 64 + r) * DIM + h * HD + c];
        qv.x *= scale; qv.y *= scale; qv.z *= scale; qv.w *= scale;
        *(float4*)&qS[r * 128 + c] = qv;
    }

    float m[8], l[8];
    float4 acc[8];
    #pragma unroll
    for (int r = 0; r < 8; r++) { m[r] = -1e30f; l[r] = 0.f; acc[r] = make_float4(0.f, 0.f, 0.f, 0.f); }

    const int row0 = qt * 64 + warp * 8;
    const int ntiles = qt * 2 + 2;

    for (int kt = 0; kt < ntiles; kt++) {
        const int kbase = kt * 32;
        __syncthreads();
        for (int i = tid; i < 32 * 32; i += 256) {
            int j = i >> 5;
            int c = i & 31;
            float4 kv = *(const float4*)&k[(size_t)(kbase + j) * KV_DIM + kvh * HD + c * 4];
            *(float4*)&kS[j * 128 + ((c ^ j) & 31) * 4] = kv;
        }
        __syncthreads();

        if (kbase <= row0 + 7) {
            float S[8] = {0.f, 0.f, 0.f, 0.f, 0.f, 0.f, 0.f, 0.f};
            const int j = lane;
            #pragma unroll 4
            for (int ci = 0; ci < 32; ci++) {
                float4 kv = *(const float4*)&kS[j * 128 + ((ci ^ j) & 31) * 4];
                #pragma unroll
                for (int r = 0; r < 8; r++) {
                    float4 qv = *(const float4*)&qS[(warp * 8 + r) * 128 + ci * 4];
                    S[r] = fmaf(qv.x, kv.x, S[r]);
                    S[r] = fmaf(qv.y, kv.y, S[r]);
                    S[r] = fmaf(qv.z, kv.z, S[r]);
                    S[r] = fmaf(qv.w, kv.w, S[r]);
                }
            }

            float P[8];
            const int kj = kbase + lane;
            #pragma unroll
            for (int r = 0; r < 8; r++) {
                const int rg = row0 + r;
                float s = (kj <= rg) ? S[r] : -1e30f;
                float tm = s;
                #pragma unroll
                for (int o = 16; o > 0; o >>= 1) tm = fmaxf(tm, __shfl_xor_sync(0xffffffffu, tm, o));
                float mn = fmaxf(m[r], tm);
                float sc = __expf(m[r] - mn);
                float p = __expf(s - mn);
                float ts = p;
                #pragma unroll
                for (int o = 16; o > 0; o >>= 1) ts += __shfl_xor_sync(0xffffffffu, ts, o);
                l[r] = l[r] * sc + ts;
                m[r] = mn;
                acc[r].x *= sc; acc[r].y *= sc; acc[r].z *= sc; acc[r].w *= sc;
                P[r] = p;
            }

            const float* vbase = v + (size_t)kbase * KV_DIM + kvh * HD + lane * 4;
            #pragma unroll 4
            for (int jj = 0; jj < 32; jj++) {
                float4 vv = *(const float4*)(vbase + (size_t)jj * KV_DIM);
                #pragma unroll
                for (int r = 0; r < 8; r++) {
                    float pj = __shfl_sync(0xffffffffu, P[r], jj);
                    acc[r].x = fmaf(pj, vv.x, acc[r].x);
                    acc[r].y = fmaf(pj, vv.y, acc[r].y);
                    acc[r].z = fmaf(pj, vv.z, acc[r].z);
                    acc[r].w = fmaf(pj, vv.w, acc[r].w);
                }
            }
        }
    }

    #pragma unroll
    for (int r = 0; r < 8; r++) {
        float inv = 1.0f / l[r];
        float4 o = acc[r];
        o.x *= inv; o.y *= inv; o.z *= inv; o.w *= inv;
        *(float4*)&y[(size_t)(row0 + r) * DIM + h * HD + lane * 4] = o;
    }
}

// ---------------------------------------------------------------------------
extern "C" void kernel_launch(void* const* d_in, const int* in_sizes, int n_in,
                              void* d_out, int out_size) {
    const float* x  = (const float*)d_in[0];
    const float* cs = (const float*)d_in[1];
    const float* sn = (const float*)d_in[2];
    const float* wq = (const float*)d_in[3];
    const float* wk = (const float*)d_in[4];
    const float* wv = (const float*)d_in[5];
    const float* wo = (const float*)d_in[6];
    const int*   sp = (const int*)d_in[7];
    float* out = (float*)d_out;

    float *q, *k, *v, *y;
    cudaGetSymbolAddress((void**)&q, g_q);
    cudaGetSymbolAddress((void**)&k, g_k);
    cudaGetSymbolAddress((void**)&v, g_v);
    cudaGetSymbolAddress((void**)&y, g_y);
    __nv_bfloat16 *xh, *xl, *yh, *yl, *wqh, *wql, *wkh, *wkl, *wvh, *wvl, *woh, *wol;
    cudaGetSymbolAddress((void**)&xh, g_xh);   cudaGetSymbolAddress((void**)&xl, g_xl);
    cudaGetSymbolAddress((void**)&yh, g_yh);   cudaGetSymbolAddress((void**)&yl, g_yl);
    cudaGetSymbolAddress((void**)&wqh, g_wqh); cudaGetSymbolAddress((void**)&wql, g_wql);
    cudaGetSymbolAddress((void**)&wkh, g_wkh); cudaGetSymbolAddress((void**)&wkl, g_wkl);
    cudaGetSymbolAddress((void**)&wvh, g_wvh); cudaGetSymbolAddress((void**)&wvl, g_wvl);
    cudaGetSymbolAddress((void**)&woh, g_woh); cudaGetSymbolAddress((void**)&wol, g_wol);

    cudaFuncSetAttribute(gemm_mma, cudaFuncAttributeMaxDynamicSharedMemorySize, GEMM_SMEM);

    dim3 blk256(256), blk128(128);
    // fp32 -> bf16 hi/lo conversions
    cvt_hilo<<<(T_SEQ * DIM / 4 + 255) / 256, blk256>>>(x, xh, xl, T_SEQ * DIM / 4);
    cvt_hilo<<<(DIM * DIM / 4 + 255) / 256, blk256>>>(wq, wqh, wql, DIM * DIM / 4);
    cvt_hilo<<<(KV_DIM * DIM / 4 + 255) / 256, blk256>>>(wk, wkh, wkl, KV_DIM * DIM / 4);
    cvt_hilo<<<(KV_DIM * DIM / 4 + 255) / 256, blk256>>>(wv, wvh, wvl, KV_DIM * DIM / 4);
    cvt_hilo<<<(DIM * DIM / 4 + 255) / 256, blk256>>>(wo, woh, wol, DIM * DIM / 4);

    // projections (tensor cores via mma.sync)
    gemm_mma<<<dim3(DIM / 128,    T_SEQ / 128), blk128, GEMM_SMEM>>>(xh, xl, wqh, wql, q, DIM,    DIM);
    gemm_mma<<<dim3(KV_DIM / 128, T_SEQ / 128), blk128, GEMM_SMEM>>>(xh, xl, wkh, wkl, k, KV_DIM, DIM);
    gemm_mma<<<dim3(KV_DIM / 128, T_SEQ / 128), blk128, GEMM_SMEM>>>(xh, xl, wvh, wvl, v, KV_DIM, DIM);

    // RoPE + attention
    rope_kernel<<<(T_SEQ * (NH + NKV) * (HD / 2) + 255) / 256, blk256>>>(q, k, cs, sn, sp);
    attn_kernel<<<dim3(T_SEQ / 64, NH), blk256>>>(q, k, v, y);

    // output projection
    cvt_hilo<<<(T_SEQ * DIM / 4 + 255) / 256, blk256>>>(y, yh, yl, T_SEQ * DIM / 4);
    gemm_mma<<<dim3(DIM / 128, T_SEQ / 128), blk128, GEMM_SMEM>>>(yh, yl, woh, wol, out, DIM, DIM);
}

// round 4
// speedup vs baseline: 3.1921x; 1.6273x over previous
#include <cuda_runtime.h>
#include <cuda_bf16.h>
#include <cuda_fp16.h>
#include <cstdint>

#define T_SEQ 2048
#define DIM 4096
#define KV_DIM 1024
#define NH 32
#define NKV 8
#define HD 128

// ---------------- scratch (__device__ globals; allocation-free rule) --------
__device__ float g_q[T_SEQ * DIM];
__device__ float g_k[T_SEQ * KV_DIM];
__device__ float g_v[T_SEQ * KV_DIM];
__device__ float g_y[T_SEQ * DIM];

__device__ __align__(16) __nv_bfloat16 g_xh[T_SEQ * DIM];
__device__ __align__(16) __nv_bfloat16 g_xl[T_SEQ * DIM];
__device__ __align__(16) __nv_bfloat16 g_yh[T_SEQ * DIM];
__device__ __align__(16) __nv_bfloat16 g_yl[T_SEQ * DIM];
__device__ __align__(16) __nv_bfloat16 g_wqh[DIM * DIM];
__device__ __align__(16) __nv_bfloat16 g_wql[DIM * DIM];
__device__ __align__(16) __nv_bfloat16 g_wkh[KV_DIM * DIM];
__device__ __align__(16) __nv_bfloat16 g_wkl[KV_DIM * DIM];
__device__ __align__(16) __nv_bfloat16 g_wvh[KV_DIM * DIM];
__device__ __align__(16) __nv_bfloat16 g_wvl[KV_DIM * DIM];
__device__ __align__(16) __nv_bfloat16 g_woh[DIM * DIM];
__device__ __align__(16) __nv_bfloat16 g_wol[DIM * DIM];
// attention operands
__device__ __align__(16) __nv_bfloat16 g_qbh[T_SEQ * DIM];
__device__ __align__(16) __nv_bfloat16 g_qbl[T_SEQ * DIM];
__device__ __align__(16) __nv_bfloat16 g_kbh[T_SEQ * KV_DIM];
__device__ __align__(16) __nv_bfloat16 g_kbl[T_SEQ * KV_DIM];
__device__ __align__(16) __half       g_vt[NKV * HD * T_SEQ];   // [kvh][hd][t]

// ---------------- portable PTX helpers (sm_80+ features only) ---------------
__device__ __forceinline__ uint32_t smem_u32(const void* p) {
    uint32_t a;
    asm("{ .reg .u64 t; cvta.to.shared.u64 t, %1; cvt.u32.u64 %0, t; }" : "=r"(a) : "l"(p));
    return a;
}
#define CP_ASYNC16(dst, src) \
    asm volatile("cp.async.cg.shared.global [%0], [%1], 16;" :: "r"(dst), "l"(src) : "memory")
#define CP_COMMIT() asm volatile("cp.async.commit_group;" ::: "memory")
#define CP_WAIT1()  asm volatile("cp.async.wait_group 1;" ::: "memory")
#define LDS32(v, addr) asm volatile("ld.shared.b32 %0, [%1];" : "=r"(v) : "r"(addr))

__device__ __forceinline__ void mma16816(float* c, const uint32_t* a, const uint32_t* b) {
    asm volatile(
        "mma.sync.aligned.m16n8k16.row.col.f32.bf16.bf16.f32 "
        "{%0,%1,%2,%3}, {%4,%5,%6,%7}, {%8,%9}, {%0,%1,%2,%3};"
        : "+f"(c[0]), "+f"(c[1]), "+f"(c[2]), "+f"(c[3])
        : "r"(a[0]), "r"(a[1]), "r"(a[2]), "r"(a[3]), "r"(b[0]), "r"(b[1]));
}
__device__ __forceinline__ void mma16816f16(float* c, const uint32_t* a, const uint32_t* b) {
    asm volatile(
        "mma.sync.aligned.m16n8k16.row.col.f32.f16.f16.f32 "
        "{%0,%1,%2,%3}, {%4,%5,%6,%7}, {%8,%9}, {%0,%1,%2,%3};"
        : "+f"(c[0]), "+f"(c[1]), "+f"(c[2]), "+f"(c[3])
        : "r"(a[0]), "r"(a[1]), "r"(a[2]), "r"(a[3]), "r"(b[0]), "r"(b[1]));
}
__device__ __forceinline__ uint32_t pack_f16(float hi, float lo) {
    uint32_t r;
    asm("cvt.rn.f16x2.f32 %0, %1, %2;" : "=r"(r) : "f"(hi), "f"(lo));
    return r;
}

// ---------------------------------------------------------------------------
// fp32 -> (bf16 hi, bf16 lo) split converter
// ---------------------------------------------------------------------------
__global__ __launch_bounds__(256) void cvt_hilo(const float* __restrict__ x,
                                                __nv_bfloat16* __restrict__ h,
                                                __nv_bfloat16* __restrict__ l, int n4) {
    int i = blockIdx.x * 256 + threadIdx.x;
    if (i >= n4) return;
    float4 v = ((const float4*)x)[i];
    __nv_bfloat16 h0 = __float2bfloat16(v.x), h1 = __float2bfloat16(v.y);
    __nv_bfloat16 h2 = __float2bfloat16(v.z), h3 = __float2bfloat16(v.w);
    __nv_bfloat16 l0 = __float2bfloat16(v.x - __bfloat162float(h0));
    __nv_bfloat16 l1 = __float2bfloat16(v.y - __bfloat162float(h1));
    __nv_bfloat16 l2 = __float2bfloat16(v.z - __bfloat162float(h2));
    __nv_bfloat16 l3 = __float2bfloat16(v.w - __bfloat162float(h3));
    ((__nv_bfloat162*)h)[2 * i]     = __nv_bfloat162(h0, h1);
    ((__nv_bfloat162*)h)[2 * i + 1] = __nv_bfloat162(h2, h3);
    ((__nv_bfloat162*)l)[2 * i]     = __nv_bfloat162(l0, l1);
    ((__nv_bfloat162*)l)[2 * i + 1] = __nv_bfloat162(l2, l3);
}

// ---------------------------------------------------------------------------
// mma.sync bf16 hi/lo GEMM (unchanged from round 3 — pipe-saturated at 267TF/s)
// ---------------------------------------------------------------------------
#define ROWP 80
#define TILEB (128 * ROWP)
#define STAGEB (4 * TILEB)
#define GEMM_SMEM (2 * STAGEB)

__global__ __launch_bounds__(128, 2) void gemm_mma(
    const __nv_bfloat16* __restrict__ Ah, const __nv_bfloat16* __restrict__ Al,
    const __nv_bfloat16* __restrict__ Bh, const __nv_bfloat16* __restrict__ Bl,
    float* __restrict__ C, int N, int K) {
    extern __shared__ char smem[];
    const uint32_t sb = smem_u32(smem);
    const int tid = threadIdx.x, warp = tid >> 5, lane = tid & 31;
    const int wm = (warp >> 1) * 64, wn = (warp & 1) * 64;
    const int m0 = blockIdx.y << 7, n0 = blockIdx.x << 7;
    const int NC = K >> 5;

    float acc[4][8][4];
    #pragma unroll
    for (int mt = 0; mt < 4; mt++)
        #pragma unroll
        for (int nt = 0; nt < 8; nt++)
            #pragma unroll
            for (int j = 0; j < 4; j++) acc[mt][nt][j] = 0.f;

    auto load_stage = [&](int kofs, int s) {
        const uint32_t base = sb + s * STAGEB;
        #pragma unroll
        for (int t = 0; t < 4; t++) {
            const __nv_bfloat16* src = (t == 0) ? Ah : (t == 1) ? Al : (t == 2) ? Bh : Bl;
            const int rb = (t < 2) ? m0 : n0;
            #pragma unroll
            for (int i = 0; i < 4; i++) {
                int idx = tid + (i << 7);
                int r = idx >> 2, c = idx & 3;
                uint32_t d = base + t * TILEB + r * ROWP + (c << 4);
                const void* g = src + (size_t)(rb + r) * K + kofs + (c << 3);
                CP_ASYNC16(d, g);
            }
        }
    };

    load_stage(0, 0);
    CP_COMMIT();
    if (NC > 1) load_stage(32, 1);
    CP_COMMIT();

    const int g4 = lane >> 2;
    const int t4 = lane & 3;

    for (int c = 0; c < NC; c++) {
        const int s = c & 1;
        CP_WAIT1();
        __syncthreads();
        const uint32_t st = sb + s * STAGEB;

        #pragma unroll
        for (int ks = 0; ks < 2; ks++) {
            const uint32_t kb = ((ks << 4) + (t4 << 1)) << 1;
            uint32_t ah[4][4], al[4][4];
            #pragma unroll
            for (int mt = 0; mt < 4; mt++) {
                uint32_t r0 = st + (wm + (mt << 4) + g4) * ROWP + kb;
                LDS32(ah[mt][0], r0);            LDS32(ah[mt][1], r0 + 8 * ROWP);
                LDS32(ah[mt][2], r0 + 16);       LDS32(ah[mt][3], r0 + 8 * ROWP + 16);
                uint32_t r1 = r0 + TILEB;
                LDS32(al[mt][0], r1);            LDS32(al[mt][1], r1 + 8 * ROWP);
                LDS32(al[mt][2], r1 + 16);       LDS32(al[mt][3], r1 + 8 * ROWP + 16);
            }
            #pragma unroll
            for (int nt = 0; nt < 8; nt++) {
                uint32_t rb0 = st + 2 * TILEB + (wn + (nt << 3) + g4) * ROWP + kb;
                uint32_t bh[2], bl[2];
                LDS32(bh[0], rb0);               LDS32(bh[1], rb0 + 16);
                LDS32(bl[0], rb0 + TILEB);       LDS32(bl[1], rb0 + TILEB + 16);
                #pragma unroll
                for (int mt = 0; mt < 4; mt++) {
                    mma16816(acc[mt][nt], ah[mt], bh);
                    mma16816(acc[mt][nt], al[mt], bh);
                    mma16816(acc[mt][nt], ah[mt], bl);
                }
            }
        }
        __syncthreads();
        if (c + 2 < NC) load_stage((c + 2) << 5, s);
        CP_COMMIT();
    }

    #pragma unroll
    for (int mt = 0; mt < 4; mt++) {
        const int row = m0 + wm + (mt << 4) + g4;
        #pragma unroll
        for (int nt = 0; nt < 8; nt++) {
            const int col = n0 + wn + (nt << 3) + (t4 << 1);
            *(float2*)&C[(size_t)row * N + col]       = make_float2(acc[mt][nt][0], acc[mt][nt][1]);
            *(float2*)&C[(size_t)(row + 8) * N + col] = make_float2(acc[mt][nt][2], acc[mt][nt][3]);
        }
    }
}

// ---------------------------------------------------------------------------
// RoPE + bf16 hi/lo conversion of q (pre-scaled) and k
// ---------------------------------------------------------------------------
__global__ __launch_bounds__(256) void rope_cvt(
    const float* __restrict__ q, const float* __restrict__ k,
    const float* __restrict__ cs, const float* __restrict__ sn,
    const int* __restrict__ spp,
    __nv_bfloat16* __restrict__ qbh, __nv_bfloat16* __restrict__ qbl,
    __nv_bfloat16* __restrict__ kbh, __nv_bfloat16* __restrict__ kbl) {
    int idx = blockIdx.x * 256 + threadIdx.x;
    const int total = T_SEQ * (NH + NKV) * (HD / 2);
    if (idx >= total) return;
    int d = idx & 63;
    int h = (idx >> 6) % (NH + NKV);
    int t = idx / (64 * (NH + NKV));
    int sp = *spp;
    float c = cs[(size_t)(sp + t) * 64 + d];
    float s = sn[(size_t)(sp + t) * 64 + d];
    const float scale = 0.08838834764831845f;   // 1/sqrt(128)

    if (h < NH) {
        size_t base = (size_t)t * DIM + h * HD;
        float x1 = q[base + d], x2 = q[base + d + 64];
        float y1 = (x1 * c - x2 * s) * scale;
        float y2 = (x2 * c + x1 * s) * scale;
        __nv_bfloat16 h1 = __float2bfloat16(y1), h2 = __float2bfloat16(y2);
        qbh[base + d] = h1;      qbl[base + d]      = __float2bfloat16(y1 - __bfloat162float(h1));
        qbh[base + d + 64] = h2; qbl[base + d + 64] = __float2bfloat16(y2 - __bfloat162float(h2));
    } else {
        size_t base = (size_t)t * KV_DIM + (h - NH) * HD;
        float x1 = k[base + d], x2 = k[base + d + 64];
        float y1 = x1 * c - x2 * s;
        float y2 = x2 * c + x1 * s;
        __nv_bfloat16 h1 = __float2bfloat16(y1), h2 = __float2bfloat16(y2);
        kbh[base + d] = h1;      kbl[base + d]      = __float2bfloat16(y1 - __bfloat162float(h1));
        kbh[base + d + 64] = h2; kbl[base + d + 64] = __float2bfloat16(y2 - __bfloat162float(h2));
    }
}

// ---------------------------------------------------------------------------
// V transpose + fp16 convert: g_vt[kvh][hd][t] = fp16(v[t][kvh*128+hd])
// ---------------------------------------------------------------------------
__global__ void vtrans(const float* __restrict__ v, __half* __restrict__ vt) {
    __shared__ float ts[32][33];
    const int kvh = blockIdx.z, db = blockIdx.y, tb = blockIdx.x;
    const int tx = threadIdx.x, ty = threadIdx.y;   // 32 x 8
    #pragma unroll
    for (int i = 0; i < 4; i++)
        ts[ty + 8 * i][tx] = v[(size_t)(tb * 32 + ty + 8 * i) * KV_DIM + kvh * HD + db * 32 + tx];
    __syncthreads();
    #pragma unroll
    for (int i = 0; i < 4; i++) {
        int dd = db * 32 + ty + 8 * i;
        vt[(size_t)(kvh * HD + dd) * T_SEQ + tb * 32 + tx] = __float2half(ts[tx][ty + 8 * i]);
    }
}

// ---------------------------------------------------------------------------
// Tensor-core causal GQA flash attention.
// Block = (q-tile 128 rows, head). 8 warps x m16 rows. K-tiles of 64 keys.
// QK^T: bf16 hi/lo 3-chain mma. P*V: fp16 single-chain mma (V^T in smem).
// Q fragments register-resident. K/V double-buffered via cp.async.
// ---------------------------------------------------------------------------
#define BK 64
#define KP 272                   // K smem row pitch (bytes)
#define VP 144                   // V^T smem row pitch
#define KST 17408                // 64*272 (one K tile)
#define VOFF 34816               // 2*KST
#define STG 53248                // VOFF + 128*144
#define ATTN_SMEM (2 * STG)      // 106496

__global__ __launch_bounds__(256, 1) void attn_tc(
    const __nv_bfloat16* __restrict__ qbh, const __nv_bfloat16* __restrict__ qbl,
    const __nv_bfloat16* __restrict__ kbh, const __nv_bfloat16* __restrict__ kbl,
    const __half* __restrict__ vt, float* __restrict__ y) {
    extern __shared__ char smem[];
    const uint32_t sb = smem_u32(smem);
    const int qt = gridDim.x - 1 - blockIdx.x;     // heavy tiles first
    const int h = blockIdx.y, kvh = h >> 2;
    const int tid = threadIdx.x, warp = tid >> 5, lane = tid & 31;
    const int g4 = lane >> 2, t4 = lane & 3;
    const int wr0 = qt * 128 + warp * 16;
    const int ntiles = 2 * qt + 2;

    // Q fragments (register-resident, loaded once)
    uint32_t qfh[8][4], qfl[8][4];
    {
        const uint32_t* ph = (const uint32_t*)qbh;
        const uint32_t* pl = (const uint32_t*)qbl;
        #pragma unroll
        for (int ks = 0; ks < 8; ks++)
            #pragma unroll
            for (int j = 0; j < 4; j++) {
                int row = wr0 + g4 + (j & 1) * 8;
                int col = 16 * ks + 2 * t4 + (j >> 1) * 8;
                size_t e = ((size_t)row * DIM + h * HD + col) >> 1;
                qfh[ks][j] = ph[e];
                qfl[ks][j] = pl[e];
            }
    }

    auto load_stage = [&](int kt, int s) {
        const uint32_t base = sb + s * STG;
        const int kbase = kt * BK;
        #pragma unroll
        for (int i = 0; i < 8; i++) {          // Kh + Kl: 2048 16B chunks
            int idx = tid + (i << 8);
            int hl = idx >> 10;
            int w = idx & 1023;
            int row = w >> 4, ch = w & 15;
            const __nv_bfloat16* src = (hl ? kbl : kbh) + (size_t)(kbase + row) * KV_DIM + kvh * HD + ch * 8;
            CP_ASYNC16(base + hl * KST + row * KP + ch * 16, src);
        }
        #pragma unroll
        for (int i = 0; i < 4; i++) {          // V^T: 1024 16B chunks
            int idx = tid + (i << 8);
            int row = idx >> 3, ch = idx & 7;
            const __half* src = vt + (size_t)(kvh * HD + row) * T_SEQ + kbase + ch * 8;
            CP_ASYNC16(base + VOFF + row * VP + ch * 16, src);
        }
    };

    float O[16][4];
    #pragma unroll
    for (int nt = 0; nt < 16; nt++)
        #pragma unroll
        for (int j = 0; j < 4; j++) O[nt][j] = 0.f;
    float m0 = -1e30f, m1 = -1e30f, l0 = 0.f, l1 = 0.f;

    load_stage(0, 0); CP_COMMIT();
    load_stage(1, 1); CP_COMMIT();

    for (int kt = 0; kt < ntiles; kt++) {
        CP_WAIT1();
        __syncthreads();
        const uint32_t stp = sb + (kt & 1) * STG;
        const int kbase = kt * BK;

        // ---- S = Q K^T (3-chain bf16) ----
        float S[8][4];
        #pragma unroll
        for (int nt = 0; nt < 8; nt++)
            #pragma unroll
            for (int j = 0; j < 4; j++) S[nt][j] = 0.f;
        #pragma unroll
        for (int ks = 0; ks < 8; ks++) {
            #pragma unroll
            for (int nt = 0; nt < 8; nt++) {
                uint32_t a0 = stp + (uint32_t)(nt * 8 + g4) * KP + (16 * ks + 2 * t4) * 2;
                uint32_t bh[2], bl[2];
                LDS32(bh[0], a0);        LDS32(bh[1], a0 + 16);
                LDS32(bl[0], a0 + KST);  LDS32(bl[1], a0 + KST + 16);
                mma16816(S[nt], qfh[ks], bh);
                mma16816(S[nt], qfl[ks], bh);
                mma16816(S[nt], qfh[ks], bl);
            }
        }

        // ---- causal mask ----
        if (kbase + BK - 1 > wr0) {
            #pragma unroll
            for (int nt = 0; nt < 8; nt++) {
                int col = kbase + nt * 8 + 2 * t4;
                int rl = wr0 + g4, rh = wr0 + 8 + g4;
                if (col     > rl) S[nt][0] = -1e30f;
                if (col + 1 > rl) S[nt][1] = -1e30f;
                if (col     > rh) S[nt][2] = -1e30f;
                if (col + 1 > rh) S[nt][3] = -1e30f;
            }
        }

        // ---- online softmax (rows g4 / g4+8) ----
        float mx0 = -1e30f, mx1 = -1e30f;
        #pragma unroll
        for (int nt = 0; nt < 8; nt++) {
            mx0 = fmaxf(mx0, fmaxf(S[nt][0], S[nt][1]));
            mx1 = fmaxf(mx1, fmaxf(S[nt][2], S[nt][3]));
        }
        mx0 = fmaxf(mx0, __shfl_xor_sync(0xffffffffu, mx0, 1));
        mx0 = fmaxf(mx0, __shfl_xor_sync(0xffffffffu, mx0, 2));
        mx1 = fmaxf(mx1, __shfl_xor_sync(0xffffffffu, mx1, 1));
        mx1 = fmaxf(mx1, __shfl_xor_sync(0xffffffffu, mx1, 2));
        float mn0 = fmaxf(m0, mx0), mn1 = fmaxf(m1, mx1);
        float a0 = __expf(m0 - mn0), a1 = __expf(m1 - mn1);
        m0 = mn0; m1 = mn1;
        float ts0 = 0.f, ts1 = 0.f;
        #pragma unroll
        for (int nt = 0; nt < 8; nt++) {
            S[nt][0] = __expf(S[nt][0] - mn0);
            S[nt][1] = __expf(S[nt][1] - mn0);
            S[nt][2] = __expf(S[nt][2] - mn1);
            S[nt][3] = __expf(S[nt][3] - mn1);
            ts0 += S[nt][0] + S[nt][1];
            ts1 += S[nt][2] + S[nt][3];
        }
        ts0 += __shfl_xor_sync(0xffffffffu, ts0, 1);
        ts0 += __shfl_xor_sync(0xffffffffu, ts0, 2);
        ts1 += __shfl_xor_sync(0xffffffffu, ts1, 1);
        ts1 += __shfl_xor_sync(0xffffffffu, ts1, 2);
        l0 = l0 * a0 + ts0;
        l1 = l1 * a1 + ts1;
        #pragma unroll
        for (int nt = 0; nt < 16; nt++) {
            O[nt][0] *= a0; O[nt][1] *= a0;
            O[nt][2] *= a1; O[nt][3] *= a1;
        }

        // ---- pack P into fp16 A-fragments ----
        uint32_t pk[4][4];
        #pragma unroll
        for (int ks = 0; ks < 4; ks++) {
            pk[ks][0] = pack_f16(S[2 * ks][1],     S[2 * ks][0]);
            pk[ks][1] = pack_f16(S[2 * ks][3],     S[2 * ks][2]);
            pk[ks][2] = pack_f16(S[2 * ks + 1][1], S[2 * ks + 1][0]);
            pk[ks][3] = pack_f16(S[2 * ks + 1][3], S[2 * ks + 1][2]);
        }

        // ---- O += P V (fp16 single-chain) ----
        #pragma unroll
        for (int ks = 0; ks < 4; ks++) {
            #pragma unroll
            for (int nt = 0; nt < 16; nt++) {
                uint32_t a0 = stp + VOFF + (uint32_t)(nt * 8 + g4) * VP + (16 * ks + 2 * t4) * 2;
                uint32_t b[2];
                LDS32(b[0], a0);
                LDS32(b[1], a0 + 16);
                mma16816f16(O[nt], pk[ks], b);
            }
        }

        __syncthreads();
        if (kt + 2 < ntiles) load_stage(kt + 2, kt & 1);
        CP_COMMIT();
    }

    // ---- epilogue ----
    float i0 = 1.f / l0, i1 = 1.f / l1;
    #pragma unroll
    for (int nt = 0; nt < 16; nt++) {
        int col = h * HD + nt * 8 + 2 * t4;
        *(float2*)&y[(size_t)(wr0 + g4) * DIM + col]     = make_float2(O[nt][0] * i0, O[nt][1] * i0);
        *(float2*)&y[(size_t)(wr0 + 8 + g4) * DIM + col] = make_float2(O[nt][2] * i1, O[nt][3] * i1);
    }
}

// ---------------------------------------------------------------------------
extern "C" void kernel_launch(void* const* d_in, const int* in_sizes, int n_in,
                              void* d_out, int out_size) {
    const float* x  = (const float*)d_in[0];
    const float* cs = (const float*)d_in[1];
    const float* sn = (const float*)d_in[2];
    const float* wq = (const float*)d_in[3];
    const float* wk = (const float*)d_in[4];
    const float* wv = (const float*)d_in[5];
    const float* wo = (const float*)d_in[6];
    const int*   sp = (const int*)d_in[7];
    float* out = (float*)d_out;

    float *q, *k, *v, *y;
    cudaGetSymbolAddress((void**)&q, g_q);
    cudaGetSymbolAddress((void**)&k, g_k);
    cudaGetSymbolAddress((void**)&v, g_v);
    cudaGetSymbolAddress((void**)&y, g_y);
    __nv_bfloat16 *xh, *xl, *yh, *yl, *wqh, *wql, *wkh, *wkl, *wvh, *wvl, *woh, *wol;
    __nv_bfloat16 *qbh, *qbl, *kbh, *kbl;
    __half* vt;
    cudaGetSymbolAddress((void**)&xh, g_xh);   cudaGetSymbolAddress((void**)&xl, g_xl);
    cudaGetSymbolAddress((void**)&yh, g_yh);   cudaGetSymbolAddress((void**)&yl, g_yl);
    cudaGetSymbolAddress((void**)&wqh, g_wqh); cudaGetSymbolAddress((void**)&wql, g_wql);
    cudaGetSymbolAddress((void**)&wkh, g_wkh); cudaGetSymbolAddress((void**)&wkl, g_wkl);
    cudaGetSymbolAddress((void**)&wvh, g_wvh); cudaGetSymbolAddress((void**)&wvl, g_wvl);
    cudaGetSymbolAddress((void**)&woh, g_woh); cudaGetSymbolAddress((void**)&wol, g_wol);
    cudaGetSymbolAddress((void**)&qbh, g_qbh); cudaGetSymbolAddress((void**)&qbl, g_qbl);
    cudaGetSymbolAddress((void**)&kbh, g_kbh); cudaGetSymbolAddress((void**)&kbl, g_kbl);
    cudaGetSymbolAddress((void**)&vt, g_vt);

    cudaFuncSetAttribute(gemm_mma, cudaFuncAttributeMaxDynamicSharedMemorySize, GEMM_SMEM);
    cudaFuncSetAttribute(attn_tc, cudaFuncAttributeMaxDynamicSharedMemorySize, ATTN_SMEM);

    dim3 blk256(256), blk128(128);
    // fp32 -> bf16 hi/lo conversions
    cvt_hilo<<<(T_SEQ * DIM / 4 + 255) / 256, blk256>>>(x, xh, xl, T_SEQ * DIM / 4);
    cvt_hilo<<<(DIM * DIM / 4 + 255) / 256, blk256>>>(wq, wqh, wql, DIM * DIM / 4);
    cvt_hilo<<<(KV_DIM * DIM / 4 + 255) / 256, blk256>>>(wk, wkh, wkl, KV_DIM * DIM / 4);
    cvt_hilo<<<(KV_DIM * DIM / 4 + 255) / 256, blk256>>>(wv, wvh, wvl, KV_DIM * DIM / 4);
    cvt_hilo<<<(DIM * DIM / 4 + 255) / 256, blk256>>>(wo, woh, wol, DIM * DIM / 4);

    // projections (tensor cores via mma.sync)
    gemm_mma<<<dim3(DIM / 128,    T_SEQ / 128), blk128, GEMM_SMEM>>>(xh, xl, wqh, wql, q, DIM,    DIM);
    gemm_mma<<<dim3(KV_DIM / 128, T_SEQ / 128), blk128, GEMM_SMEM>>>(xh, xl, wkh, wkl, k, KV_DIM, DIM);
    gemm_mma<<<dim3(KV_DIM / 128, T_SEQ / 128), blk128, GEMM_SMEM>>>(xh, xl, wvh, wvl, v, KV_DIM, DIM);

    // RoPE + attention operand prep
    rope_cvt<<<(T_SEQ * (NH + NKV) * (HD / 2) + 255) / 256, blk256>>>(
        q, k, cs, sn, sp, qbh, qbl, kbh, kbl);
    vtrans<<<dim3(T_SEQ / 32, HD / 32, NKV), dim3(32, 8)>>>(v, vt);

    // tensor-core flash attention
    attn_tc<<<dim3(T_SEQ / 128, NH), blk256, ATTN_SMEM>>>(qbh, qbl, kbh, kbl, vt, y);

    // output projection
    cvt_hilo<<<(T_SEQ * DIM / 4 + 255) / 256, blk256>>>(y, yh, yl, T_SEQ * DIM / 4);
    gemm_mma<<<dim3(DIM / 128, T_SEQ / 128), blk128, GEMM_SMEM>>>(yh, yl, woh, wol, out, DIM, DIM);
}

// round 5
// speedup vs baseline: 3.4478x; 1.0801x over previous
#include <cuda_runtime.h>
#include <cuda_bf16.h>
#include <cuda_fp16.h>
#include <cstdint>

#define T_SEQ 2048
#define DIM 4096
#define KV_DIM 1024
#define NH 32
#define NKV 8
#define HD 128

// ---------------- scratch (__device__ globals; allocation-free rule) --------
__device__ float g_q[T_SEQ * DIM];
__device__ float g_k[T_SEQ * KV_DIM];
__device__ float g_v[T_SEQ * KV_DIM];

__device__ __align__(16) __nv_bfloat16 g_xh[T_SEQ * DIM];
__device__ __align__(16) __nv_bfloat16 g_xl[T_SEQ * DIM];
__device__ __align__(16) __nv_bfloat16 g_yh[T_SEQ * DIM];
__device__ __align__(16) __nv_bfloat16 g_yl[T_SEQ * DIM];
__device__ __align__(16) __nv_bfloat16 g_wqh[DIM * DIM];
__device__ __align__(16) __nv_bfloat16 g_wql[DIM * DIM];
__device__ __align__(16) __nv_bfloat16 g_wkh[KV_DIM * DIM];
__device__ __align__(16) __nv_bfloat16 g_wkl[KV_DIM * DIM];
__device__ __align__(16) __nv_bfloat16 g_wvh[KV_DIM * DIM];
__device__ __align__(16) __nv_bfloat16 g_wvl[KV_DIM * DIM];
__device__ __align__(16) __nv_bfloat16 g_woh[DIM * DIM];
__device__ __align__(16) __nv_bfloat16 g_wol[DIM * DIM];
// attention operands
__device__ __align__(16) __nv_bfloat16 g_qbh[T_SEQ * DIM];
__device__ __align__(16) __nv_bfloat16 g_qbl[T_SEQ * DIM];
__device__ __align__(16) __nv_bfloat16 g_kbh[T_SEQ * KV_DIM];
__device__ __align__(16) __nv_bfloat16 g_kbl[T_SEQ * KV_DIM];
__device__ __align__(16) __half       g_vt[NKV * HD * T_SEQ];   // [kvh][hd][t]

// ---------------- portable PTX helpers (sm_80+ features only) ---------------
__device__ __forceinline__ uint32_t smem_u32(const void* p) {
    uint32_t a;
    asm("{ .reg .u64 t; cvta.to.shared.u64 t, %1; cvt.u32.u64 %0, t; }" : "=r"(a) : "l"(p));
    return a;
}
#define CP_ASYNC16(dst, src) \
    asm volatile("cp.async.cg.shared.global [%0], [%1], 16;" :: "r"(dst), "l"(src) : "memory")
#define CP_COMMIT() asm volatile("cp.async.commit_group;" ::: "memory")
#define CP_WAIT1()  asm volatile("cp.async.wait_group 1;" ::: "memory")
#define LDS32(v, addr) asm volatile("ld.shared.b32 %0, [%1];" : "=r"(v) : "r"(addr))
#define LDSM_X4(r0, r1, r2, r3, addr) \
    asm volatile("ldmatrix.sync.aligned.m8n8.x4.shared.b16 {%0,%1,%2,%3}, [%4];" \
        : "=r"(r0), "=r"(r1), "=r"(r2), "=r"(r3) : "r"(addr))

__device__ __forceinline__ void mma16816(float* c, const uint32_t* a, const uint32_t* b) {
    asm volatile(
        "mma.sync.aligned.m16n8k16.row.col.f32.bf16.bf16.f32 "
        "{%0,%1,%2,%3}, {%4,%5,%6,%7}, {%8,%9}, {%0,%1,%2,%3};"
        : "+f"(c[0]), "+f"(c[1]), "+f"(c[2]), "+f"(c[3])
        : "r"(a[0]), "r"(a[1]), "r"(a[2]), "r"(a[3]), "r"(b[0]), "r"(b[1]));
}
__device__ __forceinline__ void mma16816f16(float* c, const uint32_t* a, const uint32_t* b) {
    asm volatile(
        "mma.sync.aligned.m16n8k16.row.col.f32.f16.f16.f32 "
        "{%0,%1,%2,%3}, {%4,%5,%6,%7}, {%8,%9}, {%0,%1,%2,%3};"
        : "+f"(c[0]), "+f"(c[1]), "+f"(c[2]), "+f"(c[3])
        : "r"(a[0]), "r"(a[1]), "r"(a[2]), "r"(a[3]), "r"(b[0]), "r"(b[1]));
}
__device__ __forceinline__ uint32_t pack_f16(float hi, float lo) {
    uint32_t r;
    asm("cvt.rn.f16x2.f32 %0, %1, %2;" : "=r"(r) : "f"(hi), "f"(lo));
    return r;
}

// ---------------------------------------------------------------------------
// fp32 -> (bf16 hi, bf16 lo) split converter
// ---------------------------------------------------------------------------
__global__ __launch_bounds__(256) void cvt_hilo(const float* __restrict__ x,
                                                __nv_bfloat16* __restrict__ h,
                                                __nv_bfloat16* __restrict__ l, int n4) {
    int i = blockIdx.x * 256 + threadIdx.x;
    if (i >= n4) return;
    float4 v = ((const float4*)x)[i];
    __nv_bfloat16 h0 = __float2bfloat16(v.x), h1 = __float2bfloat16(v.y);
    __nv_bfloat16 h2 = __float2bfloat16(v.z), h3 = __float2bfloat16(v.w);
    __nv_bfloat16 l0 = __float2bfloat16(v.x - __bfloat162float(h0));
    __nv_bfloat16 l1 = __float2bfloat16(v.y - __bfloat162float(h1));
    __nv_bfloat16 l2 = __float2bfloat16(v.z - __bfloat162float(h2));
    __nv_bfloat16 l3 = __float2bfloat16(v.w - __bfloat162float(h3));
    ((__nv_bfloat162*)h)[2 * i]     = __nv_bfloat162(h0, h1);
    ((__nv_bfloat162*)h)[2 * i + 1] = __nv_bfloat162(h2, h3);
    ((__nv_bfloat162*)l)[2 * i]     = __nv_bfloat162(l0, l1);
    ((__nv_bfloat162*)l)[2 * i + 1] = __nv_bfloat162(l2, l3);
}

// ---------------------------------------------------------------------------
// mma.sync bf16 hi/lo GEMM v2: chain-pass ordering (no RAW stalls) + ldmatrix.
// CTA tile 128x128, BK=32, 4 warps (warp tile 64x64), cp.async double buffer.
// Row pitch 80B is conflict-free for both LDS32 and ldmatrix 8-row phases.
// ---------------------------------------------------------------------------
#define ROWP 80
#define TILEB (128 * ROWP)
#define STAGEB (4 * TILEB)
#define GEMM_SMEM (2 * STAGEB)

__global__ __launch_bounds__(128, 2) void gemm_mma(
    const __nv_bfloat16* __restrict__ Ah, const __nv_bfloat16* __restrict__ Al,
    const __nv_bfloat16* __restrict__ Bh, const __nv_bfloat16* __restrict__ Bl,
    float* __restrict__ C, int N, int K) {
    extern __shared__ char smem[];
    const uint32_t sb = smem_u32(smem);
    const int tid = threadIdx.x, warp = tid >> 5, lane = tid & 31;
    const int wm = (warp >> 1) * 64, wn = (warp & 1) * 64;
    const int m0 = blockIdx.y << 7, n0 = blockIdx.x << 7;
    const int NC = K >> 5;

    float acc[4][8][4];
    #pragma unroll
    for (int mt = 0; mt < 4; mt++)
        #pragma unroll
        for (int nt = 0; nt < 8; nt++)
            #pragma unroll
            for (int j = 0; j < 4; j++) acc[mt][nt][j] = 0.f;

    auto load_stage = [&](int kofs, int s) {
        const uint32_t base = sb + s * STAGEB;
        #pragma unroll
        for (int t = 0; t < 4; t++) {
            const __nv_bfloat16* src = (t == 0) ? Ah : (t == 1) ? Al : (t == 2) ? Bh : Bl;
            const int rb = (t < 2) ? m0 : n0;
            #pragma unroll
            for (int i = 0; i < 4; i++) {
                int idx = tid + (i << 7);
                int r = idx >> 2, c = idx & 3;
                uint32_t d = base + t * TILEB + r * ROWP + (c << 4);
                const void* g = src + (size_t)(rb + r) * K + kofs + (c << 3);
                CP_ASYNC16(d, g);
            }
        }
    };

    load_stage(0, 0);
    CP_COMMIT();
    if (NC > 1) load_stage(32, 1);
    CP_COMMIT();

    // ldmatrix lane-address components
    const uint32_t aoffA = (uint32_t)(lane & 15) * ROWP + ((lane >> 4) << 4);
    const uint32_t aoffB = (uint32_t)(((lane >> 4) << 3) + (lane & 7)) * ROWP + (((lane >> 3) & 1) << 4);

    for (int c = 0; c < NC; c++) {
        const int s = c & 1;
        CP_WAIT1();
        __syncthreads();
        const uint32_t st = sb + s * STAGEB;
        const uint32_t baseA = st + (uint32_t)wm * ROWP + aoffA;
        const uint32_t baseB = st + 2 * TILEB + (uint32_t)wn * ROWP + aoffB;

        #pragma unroll
        for (int ks = 0; ks < 2; ks++) {
            const uint32_t kb = ks << 5;   // 32B per k16
            uint32_t ah[4][4], al[4][4], bh[8][2], bl[8][2];
            #pragma unroll
            for (int mt = 0; mt < 4; mt++) {
                uint32_t a = baseA + (uint32_t)(mt * 16) * ROWP + kb;
                LDSM_X4(ah[mt][0], ah[mt][1], ah[mt][2], ah[mt][3], a);
                LDSM_X4(al[mt][0], al[mt][1], al[mt][2], al[mt][3], a + TILEB);
            }
            #pragma unroll
            for (int np = 0; np < 4; np++) {
                uint32_t b = baseB + (uint32_t)(np * 16) * ROWP + kb;
                LDSM_X4(bh[2 * np][0], bh[2 * np][1], bh[2 * np + 1][0], bh[2 * np + 1][1], b);
                LDSM_X4(bl[2 * np][0], bl[2 * np][1], bl[2 * np + 1][0], bl[2 * np + 1][1], b + TILEB);
            }
            // chain pass 1: Ah * Bh  (32 independent mma)
            #pragma unroll
            for (int nt = 0; nt < 8; nt++)
                #pragma unroll
                for (int mt = 0; mt < 4; mt++) mma16816(acc[mt][nt], ah[mt], bh[nt]);
            // chain pass 2: Al * Bh
            #pragma unroll
            for (int nt = 0; nt < 8; nt++)
                #pragma unroll
                for (int mt = 0; mt < 4; mt++) mma16816(acc[mt][nt], al[mt], bh[nt]);
            // chain pass 3: Ah * Bl
            #pragma unroll
            for (int nt = 0; nt < 8; nt++)
                #pragma unroll
                for (int mt = 0; mt < 4; mt++) mma16816(acc[mt][nt], ah[mt], bl[nt]);
        }
        __syncthreads();
        if (c + 2 < NC) load_stage((c + 2) << 5, s);
        CP_COMMIT();
    }

    const int g4 = lane >> 2, t4 = lane & 3;
    #pragma unroll
    for (int mt = 0; mt < 4; mt++) {
        const int row = m0 + wm + (mt << 4) + g4;
        #pragma unroll
        for (int nt = 0; nt < 8; nt++) {
            const int col = n0 + wn + (nt << 3) + (t4 << 1);
            *(float2*)&C[(size_t)row * N + col]       = make_float2(acc[mt][nt][0], acc[mt][nt][1]);
            *(float2*)&C[(size_t)(row + 8) * N + col] = make_float2(acc[mt][nt][2], acc[mt][nt][3]);
        }
    }
}

// ---------------------------------------------------------------------------
// RoPE + bf16 hi/lo conversion of q (pre-scaled) and k
// ---------------------------------------------------------------------------
__global__ __launch_bounds__(256) void rope_cvt(
    const float* __restrict__ q, const float* __restrict__ k,
    const float* __restrict__ cs, const float* __restrict__ sn,
    const int* __restrict__ spp,
    __nv_bfloat16* __restrict__ qbh, __nv_bfloat16* __restrict__ qbl,
    __nv_bfloat16* __restrict__ kbh, __nv_bfloat16* __restrict__ kbl) {
    int idx = blockIdx.x * 256 + threadIdx.x;
    const int total = T_SEQ * (NH + NKV) * (HD / 2);
    if (idx >= total) return;
    int d = idx & 63;
    int h = (idx >> 6) % (NH + NKV);
    int t = idx / (64 * (NH + NKV));
    int sp = *spp;
    float c = cs[(size_t)(sp + t) * 64 + d];
    float s = sn[(size_t)(sp + t) * 64 + d];
    const float scale = 0.08838834764831845f;   // 1/sqrt(128)

    if (h < NH) {
        size_t base = (size_t)t * DIM + h * HD;
        float x1 = q[base + d], x2 = q[base + d + 64];
        float y1 = (x1 * c - x2 * s) * scale;
        float y2 = (x2 * c + x1 * s) * scale;
        __nv_bfloat16 h1 = __float2bfloat16(y1), h2 = __float2bfloat16(y2);
        qbh[base + d] = h1;      qbl[base + d]      = __float2bfloat16(y1 - __bfloat162float(h1));
        qbh[base + d + 64] = h2; qbl[base + d + 64] = __float2bfloat16(y2 - __bfloat162float(h2));
    } else {
        size_t base = (size_t)t * KV_DIM + (h - NH) * HD;
        float x1 = k[base + d], x2 = k[base + d + 64];
        float y1 = x1 * c - x2 * s;
        float y2 = x2 * c + x1 * s;
        __nv_bfloat16 h1 = __float2bfloat16(y1), h2 = __float2bfloat16(y2);
        kbh[base + d] = h1;      kbl[base + d]      = __float2bfloat16(y1 - __bfloat162float(h1));
        kbh[base + d + 64] = h2; kbl[base + d + 64] = __float2bfloat16(y2 - __bfloat162float(h2));
    }
}

// ---------------------------------------------------------------------------
// V transpose + fp16 convert: g_vt[kvh][hd][t] = fp16(v[t][kvh*128+hd])
// ---------------------------------------------------------------------------
__global__ void vtrans(const float* __restrict__ v, __half* __restrict__ vt) {
    __shared__ float ts[32][33];
    const int kvh = blockIdx.z, db = blockIdx.y, tb = blockIdx.x;
    const int tx = threadIdx.x, ty = threadIdx.y;   // 32 x 8
    #pragma unroll
    for (int i = 0; i < 4; i++)
        ts[ty + 8 * i][tx] = v[(size_t)(tb * 32 + ty + 8 * i) * KV_DIM + kvh * HD + db * 32 + tx];
    __syncthreads();
    #pragma unroll
    for (int i = 0; i < 4; i++) {
        int dd = db * 32 + ty + 8 * i;
        vt[(size_t)(kvh * HD + dd) * T_SEQ + tb * 32 + tx] = __float2half(ts[tx][ty + 8 * i]);
    }
}

// ---------------------------------------------------------------------------
// Tensor-core causal GQA flash attention (round-4 core, epilogue now emits
// bf16 hi/lo directly — feeds the O-projection without an fp32 round trip).
// ---------------------------------------------------------------------------
#define BK 64
#define KP 272
#define VP 144
#define KST 17408
#define VOFF 34816
#define STG 53248
#define ATTN_SMEM (2 * STG)

__global__ __launch_bounds__(256, 1) void attn_tc(
    const __nv_bfloat16* __restrict__ qbh, const __nv_bfloat16* __restrict__ qbl,
    const __nv_bfloat16* __restrict__ kbh, const __nv_bfloat16* __restrict__ kbl,
    const __half* __restrict__ vt,
    __nv_bfloat16* __restrict__ yh, __nv_bfloat16* __restrict__ yl) {
    extern __shared__ char smem[];
    const uint32_t sb = smem_u32(smem);
    const int qt = gridDim.x - 1 - blockIdx.x;
    const int h = blockIdx.y, kvh = h >> 2;
    const int tid = threadIdx.x, warp = tid >> 5, lane = tid & 31;
    const int g4 = lane >> 2, t4 = lane & 3;
    const int wr0 = qt * 128 + warp * 16;
    const int ntiles = 2 * qt + 2;

    uint32_t qfh[8][4], qfl[8][4];
    {
        const uint32_t* ph = (const uint32_t*)qbh;
        const uint32_t* pl = (const uint32_t*)qbl;
        #pragma unroll
        for (int ks = 0; ks < 8; ks++)
            #pragma unroll
            for (int j = 0; j < 4; j++) {
                int row = wr0 + g4 + (j & 1) * 8;
                int col = 16 * ks + 2 * t4 + (j >> 1) * 8;
                size_t e = ((size_t)row * DIM + h * HD + col) >> 1;
                qfh[ks][j] = ph[e];
                qfl[ks][j] = pl[e];
            }
    }

    auto load_stage = [&](int kt, int s) {
        const uint32_t base = sb + s * STG;
        const int kbase = kt * BK;
        #pragma unroll
        for (int i = 0; i < 8; i++) {
            int idx = tid + (i << 8);
            int hl = idx >> 10;
            int w = idx & 1023;
            int row = w >> 4, ch = w & 15;
            const __nv_bfloat16* src = (hl ? kbl : kbh) + (size_t)(kbase + row) * KV_DIM + kvh * HD + ch * 8;
            CP_ASYNC16(base + hl * KST + row * KP + ch * 16, src);
        }
        #pragma unroll
        for (int i = 0; i < 4; i++) {
            int idx = tid + (i << 8);
            int row = idx >> 3, ch = idx & 7;
            const __half* src = vt + (size_t)(kvh * HD + row) * T_SEQ + kbase + ch * 8;
            CP_ASYNC16(base + VOFF + row * VP + ch * 16, src);
        }
    };

    float O[16][4];
    #pragma unroll
    for (int nt = 0; nt < 16; nt++)
        #pragma unroll
        for (int j = 0; j < 4; j++) O[nt][j] = 0.f;
    float m0 = -1e30f, m1 = -1e30f, l0 = 0.f, l1 = 0.f;

    load_stage(0, 0); CP_COMMIT();
    load_stage(1, 1); CP_COMMIT();

    for (int kt = 0; kt < ntiles; kt++) {
        CP_WAIT1();
        __syncthreads();
        const uint32_t stp = sb + (kt & 1) * STG;
        const int kbase = kt * BK;

        float S[8][4];
        #pragma unroll
        for (int nt = 0; nt < 8; nt++)
            #pragma unroll
            for (int j = 0; j < 4; j++) S[nt][j] = 0.f;
        #pragma unroll
        for (int ks = 0; ks < 8; ks++) {
            #pragma unroll
            for (int nt = 0; nt < 8; nt++) {
                uint32_t a0 = stp + (uint32_t)(nt * 8 + g4) * KP + (16 * ks + 2 * t4) * 2;
                uint32_t bh[2], bl[2];
                LDS32(bh[0], a0);        LDS32(bh[1], a0 + 16);
                LDS32(bl[0], a0 + KST);  LDS32(bl[1], a0 + KST + 16);
                mma16816(S[nt], qfh[ks], bh);
                mma16816(S[nt], qfl[ks], bh);
                mma16816(S[nt], qfh[ks], bl);
            }
        }

        if (kbase + BK - 1 > wr0) {
            #pragma unroll
            for (int nt = 0; nt < 8; nt++) {
                int col = kbase + nt * 8 + 2 * t4;
                int rl = wr0 + g4, rh = wr0 + 8 + g4;
                if (col     > rl) S[nt][0] = -1e30f;
                if (col + 1 > rl) S[nt][1] = -1e30f;
                if (col     > rh) S[nt][2] = -1e30f;
                if (col + 1 > rh) S[nt][3] = -1e30f;
            }
        }

        float mx0 = -1e30f, mx1 = -1e30f;
        #pragma unroll
        for (int nt = 0; nt < 8; nt++) {
            mx0 = fmaxf(mx0, fmaxf(S[nt][0], S[nt][1]));
            mx1 = fmaxf(mx1, fmaxf(S[nt][2], S[nt][3]));
        }
        mx0 = fmaxf(mx0, __shfl_xor_sync(0xffffffffu, mx0, 1));
        mx0 = fmaxf(mx0, __shfl_xor_sync(0xffffffffu, mx0, 2));
        mx1 = fmaxf(mx1, __shfl_xor_sync(0xffffffffu, mx1, 1));
        mx1 = fmaxf(mx1, __shfl_xor_sync(0xffffffffu, mx1, 2));
        float mn0 = fmaxf(m0, mx0), mn1 = fmaxf(m1, mx1);
        float a0 = __expf(m0 - mn0), a1 = __expf(m1 - mn1);
        m0 = mn0; m1 = mn1;
        float ts0 = 0.f, ts1 = 0.f;
        #pragma unroll
        for (int nt = 0; nt < 8; nt++) {
            S[nt][0] = __expf(S[nt][0] - mn0);
            S[nt][1] = __expf(S[nt][1] - mn0);
            S[nt][2] = __expf(S[nt][2] - mn1);
            S[nt][3] = __expf(S[nt][3] - mn1);
            ts0 += S[nt][0] + S[nt][1];
            ts1 += S[nt][2] + S[nt][3];
        }
        ts0 += __shfl_xor_sync(0xffffffffu, ts0, 1);
        ts0 += __shfl_xor_sync(0xffffffffu, ts0, 2);
        ts1 += __shfl_xor_sync(0xffffffffu, ts1, 1);
        ts1 += __shfl_xor_sync(0xffffffffu, ts1, 2);
        l0 = l0 * a0 + ts0;
        l1 = l1 * a1 + ts1;
        #pragma unroll
        for (int nt = 0; nt < 16; nt++) {
            O[nt][0] *= a0; O[nt][1] *= a0;
            O[nt][2] *= a1; O[nt][3] *= a1;
        }

        uint32_t pk[4][4];
        #pragma unroll
        for (int ks = 0; ks < 4; ks++) {
            pk[ks][0] = pack_f16(S[2 * ks][1],     S[2 * ks][0]);
            pk[ks][1] = pack_f16(S[2 * ks][3],     S[2 * ks][2]);
            pk[ks][2] = pack_f16(S[2 * ks + 1][1], S[2 * ks + 1][0]);
            pk[ks][3] = pack_f16(S[2 * ks + 1][3], S[2 * ks + 1][2]);
        }

        #pragma unroll
        for (int ks = 0; ks < 4; ks++) {
            #pragma unroll
            for (int nt = 0; nt < 16; nt++) {
                uint32_t a0 = stp + VOFF + (uint32_t)(nt * 8 + g4) * VP + (16 * ks + 2 * t4) * 2;
                uint32_t b[2];
                LDS32(b[0], a0);
                LDS32(b[1], a0 + 16);
                mma16816f16(O[nt], pk[ks], b);
            }
        }

        __syncthreads();
        if (kt + 2 < ntiles) load_stage(kt + 2, kt & 1);
        CP_COMMIT();
    }

    // ---- epilogue: write bf16 hi/lo directly (feeds O-projection) ----
    float i0 = 1.f / l0, i1 = 1.f / l1;
    #pragma unroll
    for (int nt = 0; nt < 16; nt++) {
        int col = h * HD + nt * 8 + 2 * t4;
        size_t e0 = (size_t)(wr0 + g4) * DIM + col;
        size_t e1 = (size_t)(wr0 + 8 + g4) * DIM + col;
        float v00 = O[nt][0] * i0, v01 = O[nt][1] * i0;
        float v10 = O[nt][2] * i1, v11 = O[nt][3] * i1;
        __nv_bfloat16 h00 = __float2bfloat16(v00), h01 = __float2bfloat16(v01);
        __nv_bfloat16 h10 = __float2bfloat16(v10), h11 = __float2bfloat16(v11);
        *(__nv_bfloat162*)(yh + e0) = __nv_bfloat162(h00, h01);
        *(__nv_bfloat162*)(yh + e1) = __nv_bfloat162(h10, h11);
        *(__nv_bfloat162*)(yl + e0) = __nv_bfloat162(
            __float2bfloat16(v00 - __bfloat162float(h00)),
            __float2bfloat16(v01 - __bfloat162float(h01)));
        *(__nv_bfloat162*)(yl + e1) = __nv_bfloat162(
            __float2bfloat16(v10 - __bfloat162float(h10)),
            __float2bfloat16(v11 - __bfloat162float(h11)));
    }
}

// ---------------------------------------------------------------------------
extern "C" void kernel_launch(void* const* d_in, const int* in_sizes, int n_in,
                              void* d_out, int out_size) {
    const float* x  = (const float*)d_in[0];
    const float* cs = (const float*)d_in[1];
    const float* sn = (const float*)d_in[2];
    const float* wq = (const float*)d_in[3];
    const float* wk = (const float*)d_in[4];
    const float* wv = (const float*)d_in[5];
    const float* wo = (const float*)d_in[6];
    const int*   sp = (const int*)d_in[7];
    float* out = (float*)d_out;

    float *q, *k, *v;
    cudaGetSymbolAddress((void**)&q, g_q);
    cudaGetSymbolAddress((void**)&k, g_k);
    cudaGetSymbolAddress((void**)&v, g_v);
    __nv_bfloat16 *xh, *xl, *yh, *yl, *wqh, *wql, *wkh, *wkl, *wvh, *wvl, *woh, *wol;
    __nv_bfloat16 *qbh, *qbl, *kbh, *kbl;
    __half* vt;
    cudaGetSymbolAddress((void**)&xh, g_xh);   cudaGetSymbolAddress((void**)&xl, g_xl);
    cudaGetSymbolAddress((void**)&yh, g_yh);   cudaGetSymbolAddress((void**)&yl, g_yl);
    cudaGetSymbolAddress((void**)&wqh, g_wqh); cudaGetSymbolAddress((void**)&wql, g_wql);
    cudaGetSymbolAddress((void**)&wkh, g_wkh); cudaGetSymbolAddress((void**)&wkl, g_wkl);
    cudaGetSymbolAddress((void**)&wvh, g_wvh); cudaGetSymbolAddress((void**)&wvl, g_wvl);
    cudaGetSymbolAddress((void**)&woh, g_woh); cudaGetSymbolAddress((void**)&wol, g_wol);
    cudaGetSymbolAddress((void**)&qbh, g_qbh); cudaGetSymbolAddress((void**)&qbl, g_qbl);
    cudaGetSymbolAddress((void**)&kbh, g_kbh); cudaGetSymbolAddress((void**)&kbl, g_kbl);
    cudaGetSymbolAddress((void**)&vt, g_vt);

    cudaFuncSetAttribute(gemm_mma, cudaFuncAttributeMaxDynamicSharedMemorySize, GEMM_SMEM);
    cudaFuncSetAttribute(attn_tc, cudaFuncAttributeMaxDynamicSharedMemorySize, ATTN_SMEM);

    dim3 blk256(256), blk128(128);
    cvt_hilo<<<(T_SEQ * DIM / 4 + 255) / 256, blk256>>>(x, xh, xl, T_SEQ * DIM / 4);
    cvt_hilo<<<(DIM * DIM / 4 + 255) / 256, blk256>>>(wq, wqh, wql, DIM * DIM / 4);
    cvt_hilo<<<(KV_DIM * DIM / 4 + 255) / 256, blk256>>>(wk, wkh, wkl, KV_DIM * DIM / 4);
    cvt_hilo<<<(KV_DIM * DIM / 4 + 255) / 256, blk256>>>(wv, wvh, wvl, KV_DIM * DIM / 4);
    cvt_hilo<<<(DIM * DIM / 4 + 255) / 256, blk256>>>(wo, woh, wol, DIM * DIM / 4);

    gemm_mma<<<dim3(DIM / 128,    T_SEQ / 128), blk128, GEMM_SMEM>>>(xh, xl, wqh, wql, q, DIM,    DIM);
    gemm_mma<<<dim3(KV_DIM / 128, T_SEQ / 128), blk128, GEMM_SMEM>>>(xh, xl, wkh, wkl, k, KV_DIM, DIM);
    gemm_mma<<<dim3(KV_DIM / 128, T_SEQ / 128), blk128, GEMM_SMEM>>>(xh, xl, wvh, wvl, v, KV_DIM, DIM);

    rope_cvt<<<(T_SEQ * (NH + NKV) * (HD / 2) + 255) / 256, blk256>>>(
        q, k, cs, sn, sp, qbh, qbl, kbh, kbl);
    vtrans<<<dim3(T_SEQ / 32, HD / 32, NKV), dim3(32, 8)>>>(v, vt);

    attn_tc<<<dim3(T_SEQ / 128, NH), blk256, ATTN_SMEM>>>(qbh, qbl, kbh, kbl, vt, yh, yl);

    gemm_mma<<<dim3(DIM / 128, T_SEQ / 128), blk128, GEMM_SMEM>>>(yh, yl, woh, wol, out, DIM, DIM);
}

// round 6
// speedup vs baseline: 4.3151x; 1.2515x over previous
#include <cuda_runtime.h>
#include <cuda_bf16.h>
#include <cuda_fp16.h>
#include <cstdint>

#define T_SEQ 2048
#define DIM 4096
#define KV_DIM 1024
#define NH 32
#define NKV 8
#define HD 128

// ---------------- scratch (__device__ globals; allocation-free rule) --------
__device__ float g_q[T_SEQ * DIM];
__device__ float g_k[T_SEQ * KV_DIM];
__device__ float g_v[T_SEQ * KV_DIM];

__device__ __align__(16) __half g_xh[T_SEQ * DIM];
__device__ __align__(16) __half g_xl[T_SEQ * DIM];
__device__ __align__(16) __half g_yh[T_SEQ * DIM];
__device__ __align__(16) __half g_yl[T_SEQ * DIM];
__device__ __align__(16) __half g_wqh[DIM * DIM];
__device__ __align__(16) __half g_wkh[KV_DIM * DIM];
__device__ __align__(16) __half g_wvh[KV_DIM * DIM];
__device__ __align__(16) __half g_woh[DIM * DIM];
// attention operands (fp16 hi/lo)
__device__ __align__(16) __half g_qbh[T_SEQ * DIM];
__device__ __align__(16) __half g_qbl[T_SEQ * DIM];
__device__ __align__(16) __half g_kbh[T_SEQ * KV_DIM];
__device__ __align__(16) __half g_kbl[T_SEQ * KV_DIM];
__device__ __align__(16) __half g_vt[NKV * HD * T_SEQ];   // [kvh][hd][t]

// ---------------- portable PTX helpers (sm_80+ features only) ---------------
__device__ __forceinline__ uint32_t smem_u32(const void* p) {
    uint32_t a;
    asm("{ .reg .u64 t; cvta.to.shared.u64 t, %1; cvt.u32.u64 %0, t; }" : "=r"(a) : "l"(p));
    return a;
}
#define CP_ASYNC16(dst, src) \
    asm volatile("cp.async.cg.shared.global [%0], [%1], 16;" :: "r"(dst), "l"(src) : "memory")
#define CP_COMMIT() asm volatile("cp.async.commit_group;" ::: "memory")
#define CP_WAIT1()  asm volatile("cp.async.wait_group 1;" ::: "memory")
#define LDS32(v, addr) asm volatile("ld.shared.b32 %0, [%1];" : "=r"(v) : "r"(addr))
#define LDSM_X4(r0, r1, r2, r3, addr) \
    asm volatile("ldmatrix.sync.aligned.m8n8.x4.shared.b16 {%0,%1,%2,%3}, [%4];" \
        : "=r"(r0), "=r"(r1), "=r"(r2), "=r"(r3) : "r"(addr))

__device__ __forceinline__ void mma16816f16(float* c, const uint32_t* a, const uint32_t* b) {
    asm volatile(
        "mma.sync.aligned.m16n8k16.row.col.f32.f16.f16.f32 "
        "{%0,%1,%2,%3}, {%4,%5,%6,%7}, {%8,%9}, {%0,%1,%2,%3};"
        : "+f"(c[0]), "+f"(c[1]), "+f"(c[2]), "+f"(c[3])
        : "r"(a[0]), "r"(a[1]), "r"(a[2]), "r"(a[3]), "r"(b[0]), "r"(b[1]));
}
__device__ __forceinline__ uint32_t pack_f16(float hi, float lo) {
    uint32_t r;
    asm("cvt.rn.f16x2.f32 %0, %1, %2;" : "=r"(r) : "f"(hi), "f"(lo));
    return r;
}

// ---------------------------------------------------------------------------
// fp32 -> (fp16 hi, fp16 lo) split (for activations)
// ---------------------------------------------------------------------------
__global__ __launch_bounds__(256) void cvt_hilo_f16(const float* __restrict__ x,
                                                    __half* __restrict__ h,
                                                    __half* __restrict__ l, int n4) {
    int i = blockIdx.x * 256 + threadIdx.x;
    if (i >= n4) return;
    float4 v = ((const float4*)x)[i];
    __half h0 = __float2half(v.x), h1 = __float2half(v.y);
    __half h2 = __float2half(v.z), h3 = __float2half(v.w);
    __half l0 = __float2half(v.x - __half2float(h0));
    __half l1 = __float2half(v.y - __half2float(h1));
    __half l2 = __float2half(v.z - __half2float(h2));
    __half l3 = __float2half(v.w - __half2float(h3));
    ((__half2*)h)[2 * i]     = __halves2half2(h0, h1);
    ((__half2*)h)[2 * i + 1] = __halves2half2(h2, h3);
    ((__half2*)l)[2 * i]     = __halves2half2(l0, l1);
    ((__half2*)l)[2 * i + 1] = __halves2half2(l2, l3);
}

// fp32 -> fp16 (for weights; 2-chain uses B-hi only)
__global__ __launch_bounds__(256) void cvt_f16(const float* __restrict__ x,
                                               __half* __restrict__ h, int n4) {
    int i = blockIdx.x * 256 + threadIdx.x;
    if (i >= n4) return;
    float4 v = ((const float4*)x)[i];
    ((__half2*)h)[2 * i]     = __halves2half2(__float2half(v.x), __float2half(v.y));
    ((__half2*)h)[2 * i + 1] = __halves2half2(__float2half(v.z), __float2half(v.w));
}

// ---------------------------------------------------------------------------
// mma.sync fp16 2-chain GEMM: C[M x N] = (Ah+Al)[M x K] * Bh[N x K]^T
// CTA tile 128x128, BK=32, 4 warps, chain-pass ordering, cp.async 2-stage.
// ---------------------------------------------------------------------------
#define ROWP 80
#define TILEB (128 * ROWP)        // 10240
#define STAGEB (3 * TILEB)        // 30720 (Ah, Al, Bh)
#define GEMM_SMEM (2 * STAGEB)    // 61440

__global__ __launch_bounds__(128, 2) void gemm_mma(
    const __half* __restrict__ Ah, const __half* __restrict__ Al,
    const __half* __restrict__ Bh,
    float* __restrict__ C, int N, int K) {
    extern __shared__ char smem[];
    const uint32_t sb = smem_u32(smem);
    const int tid = threadIdx.x, warp = tid >> 5, lane = tid & 31;
    const int wm = (warp >> 1) * 64, wn = (warp & 1) * 64;
    const int m0 = blockIdx.y << 7, n0 = blockIdx.x << 7;
    const int NC = K >> 5;

    float acc[4][8][4];
    #pragma unroll
    for (int mt = 0; mt < 4; mt++)
        #pragma unroll
        for (int nt = 0; nt < 8; nt++)
            #pragma unroll
            for (int j = 0; j < 4; j++) acc[mt][nt][j] = 0.f;

    auto load_stage = [&](int kofs, int s) {
        const uint32_t base = sb + s * STAGEB;
        #pragma unroll
        for (int t = 0; t < 3; t++) {
            const __half* src = (t == 0) ? Ah : (t == 1) ? Al : Bh;
            const int rb = (t < 2) ? m0 : n0;
            #pragma unroll
            for (int i = 0; i < 4; i++) {
                int idx = tid + (i << 7);
                int r = idx >> 2, c = idx & 3;
                uint32_t d = base + t * TILEB + r * ROWP + (c << 4);
                const void* g = src + (size_t)(rb + r) * K + kofs + (c << 3);
                CP_ASYNC16(d, g);
            }
        }
    };

    load_stage(0, 0);
    CP_COMMIT();
    if (NC > 1) load_stage(32, 1);
    CP_COMMIT();

    const uint32_t aoffA = (uint32_t)(lane & 15) * ROWP + ((lane >> 4) << 4);
    const uint32_t aoffB = (uint32_t)(((lane >> 4) << 3) + (lane & 7)) * ROWP + (((lane >> 3) & 1) << 4);

    for (int c = 0; c < NC; c++) {
        const int s = c & 1;
        CP_WAIT1();
        __syncthreads();
        const uint32_t st = sb + s * STAGEB;
        const uint32_t baseA = st + (uint32_t)wm * ROWP + aoffA;
        const uint32_t baseB = st + 2 * TILEB + (uint32_t)wn * ROWP + aoffB;

        #pragma unroll
        for (int ks = 0; ks < 2; ks++) {
            const uint32_t kb = ks << 5;
            uint32_t ah[4][4], al[4][4], bh[8][2];
            #pragma unroll
            for (int mt = 0; mt < 4; mt++) {
                uint32_t a = baseA + (uint32_t)(mt * 16) * ROWP + kb;
                LDSM_X4(ah[mt][0], ah[mt][1], ah[mt][2], ah[mt][3], a);
                LDSM_X4(al[mt][0], al[mt][1], al[mt][2], al[mt][3], a + TILEB);
            }
            #pragma unroll
            for (int np = 0; np < 4; np++) {
                uint32_t b = baseB + (uint32_t)(np * 16) * ROWP + kb;
                LDSM_X4(bh[2 * np][0], bh[2 * np][1], bh[2 * np + 1][0], bh[2 * np + 1][1], b);
            }
            // chain pass 1: Ah * Bh (32 independent mma)
            #pragma unroll
            for (int nt = 0; nt < 8; nt++)
                #pragma unroll
                for (int mt = 0; mt < 4; mt++) mma16816f16(acc[mt][nt], ah[mt], bh[nt]);
            // chain pass 2: Al * Bh
            #pragma unroll
            for (int nt = 0; nt < 8; nt++)
                #pragma unroll
                for (int mt = 0; mt < 4; mt++) mma16816f16(acc[mt][nt], al[mt], bh[nt]);
        }
        __syncthreads();
        if (c + 2 < NC) load_stage((c + 2) << 5, s);
        CP_COMMIT();
    }

    const int g4 = lane >> 2, t4 = lane & 3;
    #pragma unroll
    for (int mt = 0; mt < 4; mt++) {
        const int row = m0 + wm + (mt << 4) + g4;
        #pragma unroll
        for (int nt = 0; nt < 8; nt++) {
            const int col = n0 + wn + (nt << 3) + (t4 << 1);
            *(float2*)&C[(size_t)row * N + col]       = make_float2(acc[mt][nt][0], acc[mt][nt][1]);
            *(float2*)&C[(size_t)(row + 8) * N + col] = make_float2(acc[mt][nt][2], acc[mt][nt][3]);
        }
    }
}

// ---------------------------------------------------------------------------
// RoPE + fp16 hi/lo conversion of q (pre-scaled) and k
// ---------------------------------------------------------------------------
__global__ __launch_bounds__(256) void rope_cvt(
    const float* __restrict__ q, const float* __restrict__ k,
    const float* __restrict__ cs, const float* __restrict__ sn,
    const int* __restrict__ spp,
    __half* __restrict__ qbh, __half* __restrict__ qbl,
    __half* __restrict__ kbh, __half* __restrict__ kbl) {
    int idx = blockIdx.x * 256 + threadIdx.x;
    const int total = T_SEQ * (NH + NKV) * (HD / 2);
    if (idx >= total) return;
    int d = idx & 63;
    int h = (idx >> 6) % (NH + NKV);
    int t = idx / (64 * (NH + NKV));
    int sp = *spp;
    float c = cs[(size_t)(sp + t) * 64 + d];
    float s = sn[(size_t)(sp + t) * 64 + d];
    const float scale = 0.08838834764831845f;   // 1/sqrt(128)

    if (h < NH) {
        size_t base = (size_t)t * DIM + h * HD;
        float x1 = q[base + d], x2 = q[base + d + 64];
        float y1 = (x1 * c - x2 * s) * scale;
        float y2 = (x2 * c + x1 * s) * scale;
        __half h1 = __float2half(y1), h2 = __float2half(y2);
        qbh[base + d] = h1;      qbl[base + d]      = __float2half(y1 - __half2float(h1));
        qbh[base + d + 64] = h2; qbl[base + d + 64] = __float2half(y2 - __half2float(h2));
    } else {
        size_t base = (size_t)t * KV_DIM + (h - NH) * HD;
        float x1 = k[base + d], x2 = k[base + d + 64];
        float y1 = x1 * c - x2 * s;
        float y2 = x2 * c + x1 * s;
        __half h1 = __float2half(y1), h2 = __float2half(y2);
        kbh[base + d] = h1;      kbl[base + d]      = __float2half(y1 - __half2float(h1));
        kbh[base + d + 64] = h2; kbl[base + d + 64] = __float2half(y2 - __half2float(h2));
    }
}

// ---------------------------------------------------------------------------
// V transpose + fp16 convert
// ---------------------------------------------------------------------------
__global__ void vtrans(const float* __restrict__ v, __half* __restrict__ vt) {
    __shared__ float ts[32][33];
    const int kvh = blockIdx.z, db = blockIdx.y, tb = blockIdx.x;
    const int tx = threadIdx.x, ty = threadIdx.y;   // 32 x 8
    #pragma unroll
    for (int i = 0; i < 4; i++)
        ts[ty + 8 * i][tx] = v[(size_t)(tb * 32 + ty + 8 * i) * KV_DIM + kvh * HD + db * 32 + tx];
    __syncthreads();
    #pragma unroll
    for (int i = 0; i < 4; i++) {
        int dd = db * 32 + ty + 8 * i;
        vt[(size_t)(kvh * HD + dd) * T_SEQ + tb * 32 + tx] = __float2half(ts[tx][ty + 8 * i]);
    }
}

// ---------------------------------------------------------------------------
// Tensor-core causal GQA flash attention.
// QK^T: fp16 hi/lo 3-chain (near-exact scores). P*V: fp16 single-chain.
// Epilogue emits fp16 hi/lo for the O-projection (no fp32 round trip).
// ---------------------------------------------------------------------------
#define BK 64
#define KP 272
#define VP 144
#define KST 17408
#define VOFF 34816
#define STG 53248
#define ATTN_SMEM (2 * STG)

__global__ __launch_bounds__(256, 1) void attn_tc(
    const __half* __restrict__ qbh, const __half* __restrict__ qbl,
    const __half* __restrict__ kbh, const __half* __restrict__ kbl,
    const __half* __restrict__ vt,
    __half* __restrict__ yh, __half* __restrict__ yl) {
    extern __shared__ char smem[];
    const uint32_t sb = smem_u32(smem);
    const int qt = gridDim.x - 1 - blockIdx.x;
    const int h = blockIdx.y, kvh = h >> 2;
    const int tid = threadIdx.x, warp = tid >> 5, lane = tid & 31;
    const int g4 = lane >> 2, t4 = lane & 3;
    const int wr0 = qt * 128 + warp * 16;
    const int ntiles = 2 * qt + 2;

    uint32_t qfh[8][4], qfl[8][4];
    {
        const uint32_t* ph = (const uint32_t*)qbh;
        const uint32_t* pl = (const uint32_t*)qbl;
        #pragma unroll
        for (int ks = 0; ks < 8; ks++)
            #pragma unroll
            for (int j = 0; j < 4; j++) {
                int row = wr0 + g4 + (j & 1) * 8;
                int col = 16 * ks + 2 * t4 + (j >> 1) * 8;
                size_t e = ((size_t)row * DIM + h * HD + col) >> 1;
                qfh[ks][j] = ph[e];
                qfl[ks][j] = pl[e];
            }
    }

    auto load_stage = [&](int kt, int s) {
        const uint32_t base = sb + s * STG;
        const int kbase = kt * BK;
        #pragma unroll
        for (int i = 0; i < 8; i++) {
            int idx = tid + (i << 8);
            int hl = idx >> 10;
            int w = idx & 1023;
            int row = w >> 4, ch = w & 15;
            const __half* src = (hl ? kbl : kbh) + (size_t)(kbase + row) * KV_DIM + kvh * HD + ch * 8;
            CP_ASYNC16(base + hl * KST + row * KP + ch * 16, src);
        }
        #pragma unroll
        for (int i = 0; i < 4; i++) {
            int idx = tid + (i << 8);
            int row = idx >> 3, ch = idx & 7;
            const __half* src = vt + (size_t)(kvh * HD + row) * T_SEQ + kbase + ch * 8;
            CP_ASYNC16(base + VOFF + row * VP + ch * 16, src);
        }
    };

    float O[16][4];
    #pragma unroll
    for (int nt = 0; nt < 16; nt++)
        #pragma unroll
        for (int j = 0; j < 4; j++) O[nt][j] = 0.f;
    float m0 = -1e30f, m1 = -1e30f, l0 = 0.f, l1 = 0.f;

    load_stage(0, 0); CP_COMMIT();
    load_stage(1, 1); CP_COMMIT();

    for (int kt = 0; kt < ntiles; kt++) {
        CP_WAIT1();
        __syncthreads();
        const uint32_t stp = sb + (kt & 1) * STG;
        const int kbase = kt * BK;

        float S[8][4];
        #pragma unroll
        for (int nt = 0; nt < 8; nt++)
            #pragma unroll
            for (int j = 0; j < 4; j++) S[nt][j] = 0.f;
        #pragma unroll
        for (int ks = 0; ks < 8; ks++) {
            #pragma unroll
            for (int nt = 0; nt < 8; nt++) {
                uint32_t a0 = stp + (uint32_t)(nt * 8 + g4) * KP + (16 * ks + 2 * t4) * 2;
                uint32_t bh[2], bl[2];
                LDS32(bh[0], a0);        LDS32(bh[1], a0 + 16);
                LDS32(bl[0], a0 + KST);  LDS32(bl[1], a0 + KST + 16);
                mma16816f16(S[nt], qfh[ks], bh);
                mma16816f16(S[nt], qfl[ks], bh);
                mma16816f16(S[nt], qfh[ks], bl);
            }
        }

        if (kbase + BK - 1 > wr0) {
            #pragma unroll
            for (int nt = 0; nt < 8; nt++) {
                int col = kbase + nt * 8 + 2 * t4;
                int rl = wr0 + g4, rh = wr0 + 8 + g4;
                if (col     > rl) S[nt][0] = -1e30f;
                if (col + 1 > rl) S[nt][1] = -1e30f;
                if (col     > rh) S[nt][2] = -1e30f;
                if (col + 1 > rh) S[nt][3] = -1e30f;
            }
        }

        float mx0 = -1e30f, mx1 = -1e30f;
        #pragma unroll
        for (int nt = 0; nt < 8; nt++) {
            mx0 = fmaxf(mx0, fmaxf(S[nt][0], S[nt][1]));
            mx1 = fmaxf(mx1, fmaxf(S[nt][2], S[nt][3]));
        }
        mx0 = fmaxf(mx0, __shfl_xor_sync(0xffffffffu, mx0, 1));
        mx0 = fmaxf(mx0, __shfl_xor_sync(0xffffffffu, mx0, 2));
        mx1 = fmaxf(mx1, __shfl_xor_sync(0xffffffffu, mx1, 1));
        mx1 = fmaxf(mx1, __shfl_xor_sync(0xffffffffu, mx1, 2));
        float mn0 = fmaxf(m0, mx0), mn1 = fmaxf(m1, mx1);
        float a0 = __expf(m0 - mn0), a1 = __expf(m1 - mn1);
        m0 = mn0; m1 = mn1;
        float ts0 = 0.f, ts1 = 0.f;
        #pragma unroll
        for (int nt = 0; nt < 8; nt++) {
            S[nt][0] = __expf(S[nt][0] - mn0);
            S[nt][1] = __expf(S[nt][1] - mn0);
            S[nt][2] = __expf(S[nt][2] - mn1);
            S[nt][3] = __expf(S[nt][3] - mn1);
            ts0 += S[nt][0] + S[nt][1];
            ts1 += S[nt][2] + S[nt][3];
        }
        ts0 += __shfl_xor_sync(0xffffffffu, ts0, 1);
        ts0 += __shfl_xor_sync(0xffffffffu, ts0, 2);
        ts1 += __shfl_xor_sync(0xffffffffu, ts1, 1);
        ts1 += __shfl_xor_sync(0xffffffffu, ts1, 2);
        l0 = l0 * a0 + ts0;
        l1 = l1 * a1 + ts1;
        #pragma unroll
        for (int nt = 0; nt < 16; nt++) {
            O[nt][0] *= a0; O[nt][1] *= a0;
            O[nt][2] *= a1; O[nt][3] *= a1;
        }

        uint32_t pk[4][4];
        #pragma unroll
        for (int ks = 0; ks < 4; ks++) {
            pk[ks][0] = pack_f16(S[2 * ks][1],     S[2 * ks][0]);
            pk[ks][1] = pack_f16(S[2 * ks][3],     S[2 * ks][2]);
            pk[ks][2] = pack_f16(S[2 * ks + 1][1], S[2 * ks + 1][0]);
            pk[ks][3] = pack_f16(S[2 * ks + 1][3], S[2 * ks + 1][2]);
        }

        #pragma unroll
        for (int ks = 0; ks < 4; ks++) {
            #pragma unroll
            for (int nt = 0; nt < 16; nt++) {
                uint32_t a0 = stp + VOFF + (uint32_t)(nt * 8 + g4) * VP + (16 * ks + 2 * t4) * 2;
                uint32_t b[2];
                LDS32(b[0], a0);
                LDS32(b[1], a0 + 16);
                mma16816f16(O[nt], pk[ks], b);
            }
        }

        __syncthreads();
        if (kt + 2 < ntiles) load_stage(kt + 2, kt & 1);
        CP_COMMIT();
    }

    // ---- epilogue: write fp16 hi/lo (feeds 2-chain O-projection) ----
    float i0 = 1.f / l0, i1 = 1.f / l1;
    #pragma unroll
    for (int nt = 0; nt < 16; nt++) {
        int col = h * HD + nt * 8 + 2 * t4;
        size_t e0 = (size_t)(wr0 + g4) * DIM + col;
        size_t e1 = (size_t)(wr0 + 8 + g4) * DIM + col;
        float v00 = O[nt][0] * i0, v01 = O[nt][1] * i0;
        float v10 = O[nt][2] * i1, v11 = O[nt][3] * i1;
        __half h00 = __float2half(v00), h01 = __float2half(v01);
        __half h10 = __float2half(v10), h11 = __float2half(v11);
        *(__half2*)(yh + e0) = __halves2half2(h00, h01);
        *(__half2*)(yh + e1) = __halves2half2(h10, h11);
        *(__half2*)(yl + e0) = __halves2half2(
            __float2half(v00 - __half2float(h00)), __float2half(v01 - __half2float(h01)));
        *(__half2*)(yl + e1) = __halves2half2(
            __float2half(v10 - __half2float(h10)), __float2half(v11 - __half2float(h11)));
    }
}

// ---------------------------------------------------------------------------
extern "C" void kernel_launch(void* const* d_in, const int* in_sizes, int n_in,
                              void* d_out, int out_size) {
    const float* x  = (const float*)d_in[0];
    const float* cs = (const float*)d_in[1];
    const float* sn = (const float*)d_in[2];
    const float* wq = (const float*)d_in[3];
    const float* wk = (const float*)d_in[4];
    const float* wv = (const float*)d_in[5];
    const float* wo = (const float*)d_in[6];
    const int*   sp = (const int*)d_in[7];
    float* out = (float*)d_out;

    float *q, *k, *v;
    cudaGetSymbolAddress((void**)&q, g_q);
    cudaGetSymbolAddress((void**)&k, g_k);
    cudaGetSymbolAddress((void**)&v, g_v);
    __half *xh, *xl, *yh, *yl, *wqh, *wkh, *wvh, *woh;
    __half *qbh, *qbl, *kbh, *kbl, *vt;
    cudaGetSymbolAddress((void**)&xh, g_xh);   cudaGetSymbolAddress((void**)&xl, g_xl);
    cudaGetSymbolAddress((void**)&yh, g_yh);   cudaGetSymbolAddress((void**)&yl, g_yl);
    cudaGetSymbolAddress((void**)&wqh, g_wqh); cudaGetSymbolAddress((void**)&wkh, g_wkh);
    cudaGetSymbolAddress((void**)&wvh, g_wvh); cudaGetSymbolAddress((void**)&woh, g_woh);
    cudaGetSymbolAddress((void**)&qbh, g_qbh); cudaGetSymbolAddress((void**)&qbl, g_qbl);
    cudaGetSymbolAddress((void**)&kbh, g_kbh); cudaGetSymbolAddress((void**)&kbl, g_kbl);
    cudaGetSymbolAddress((void**)&vt, g_vt);

    cudaFuncSetAttribute(gemm_mma, cudaFuncAttributeMaxDynamicSharedMemorySize, GEMM_SMEM);
    cudaFuncSetAttribute(attn_tc, cudaFuncAttributeMaxDynamicSharedMemorySize, ATTN_SMEM);

    dim3 blk256(256), blk128(128);
    // conversions: x -> fp16 hi/lo, weights -> fp16 hi only
    cvt_hilo_f16<<<(T_SEQ * DIM / 4 + 255) / 256, blk256>>>(x, xh, xl, T_SEQ * DIM / 4);
    cvt_f16<<<(DIM * DIM / 4 + 255) / 256, blk256>>>(wq, wqh, DIM * DIM / 4);
    cvt_f16<<<(KV_DIM * DIM / 4 + 255) / 256, blk256>>>(wk, wkh, KV_DIM * DIM / 4);
    cvt_f16<<<(KV_DIM * DIM / 4 + 255) / 256, blk256>>>(wv, wvh, KV_DIM * DIM / 4);
    cvt_f16<<<(DIM * DIM / 4 + 255) / 256, blk256>>>(wo, woh, DIM * DIM / 4);

    // projections (fp16 2-chain)
    gemm_mma<<<dim3(DIM / 128,    T_SEQ / 128), blk128, GEMM_SMEM>>>(xh, xl, wqh, q, DIM,    DIM);
    gemm_mma<<<dim3(KV_DIM / 128, T_SEQ / 128), blk128, GEMM_SMEM>>>(xh, xl, wkh, k, KV_DIM, DIM);
    gemm_mma<<<dim3(KV_DIM / 128, T_SEQ / 128), blk128, GEMM_SMEM>>>(xh, xl, wvh, v, KV_DIM, DIM);

    rope_cvt<<<(T_SEQ * (NH + NKV) * (HD / 2) + 255) / 256, blk256>>>(
        q, k, cs, sn, sp, qbh, qbl, kbh, kbl);
    vtrans<<<dim3(T_SEQ / 32, HD / 32, NKV), dim3(32, 8)>>>(v, vt);

    attn_tc<<<dim3(T_SEQ / 128, NH), blk256, ATTN_SMEM>>>(qbh, qbl, kbh, kbl, vt, yh, yl);

    // output projection (fp16 2-chain)
    gemm_mma<<<dim3(DIM / 128, T_SEQ / 128), blk128, GEMM_SMEM>>>(yh, yl, woh, out, DIM, DIM);
}

// round 7
// speedup vs baseline: 4.4834x; 1.0390x over previous
#include <cuda_runtime.h>
#include <cuda_bf16.h>
#include <cuda_fp16.h>
#include <cstdint>

#define T_SEQ 2048
#define DIM 4096
#define KV_DIM 1024
#define NH 32
#define NKV 8
#define HD 128

// ---------------- scratch (__device__ globals; allocation-free rule) --------
__device__ __align__(16) __half g_xh[T_SEQ * DIM];
__device__ __align__(16) __half g_xl[T_SEQ * DIM];
__device__ __align__(16) __half g_yh[T_SEQ * DIM];
__device__ __align__(16) __half g_yl[T_SEQ * DIM];
__device__ __align__(16) __half g_wqh[DIM * DIM];
__device__ __align__(16) __half g_wkh[KV_DIM * DIM];
__device__ __align__(16) __half g_wvh[KV_DIM * DIM];
__device__ __align__(16) __half g_woh[DIM * DIM];
// attention operands (fp16 hi/lo)
__device__ __align__(16) __half g_qbh[T_SEQ * DIM];
__device__ __align__(16) __half g_qbl[T_SEQ * DIM];
__device__ __align__(16) __half g_kbh[T_SEQ * KV_DIM];
__device__ __align__(16) __half g_kbl[T_SEQ * KV_DIM];
__device__ __align__(16) __half g_vt[NKV * HD * T_SEQ];   // [kvh][hd][t]

// ---------------- portable PTX helpers (sm_80+ features only) ---------------
__device__ __forceinline__ uint32_t smem_u32(const void* p) {
    uint32_t a;
    asm("{ .reg .u64 t; cvta.to.shared.u64 t, %1; cvt.u32.u64 %0, t; }" : "=r"(a) : "l"(p));
    return a;
}
#define CP_ASYNC16(dst, src) \
    asm volatile("cp.async.cg.shared.global [%0], [%1], 16;" :: "r"(dst), "l"(src) : "memory")
#define CP_COMMIT() asm volatile("cp.async.commit_group;" ::: "memory")
#define CP_WAIT1()  asm volatile("cp.async.wait_group 1;" ::: "memory")
#define LDS32(v, addr) asm volatile("ld.shared.b32 %0, [%1];" : "=r"(v) : "r"(addr))
#define LDSM_X4(r0, r1, r2, r3, addr) \
    asm volatile("ldmatrix.sync.aligned.m8n8.x4.shared.b16 {%0,%1,%2,%3}, [%4];" \
        : "=r"(r0), "=r"(r1), "=r"(r2), "=r"(r3) : "r"(addr))

__device__ __forceinline__ void mma16816f16(float* c, const uint32_t* a, const uint32_t* b) {
    asm volatile(
        "mma.sync.aligned.m16n8k16.row.col.f32.f16.f16.f32 "
        "{%0,%1,%2,%3}, {%4,%5,%6,%7}, {%8,%9}, {%0,%1,%2,%3};"
        : "+f"(c[0]), "+f"(c[1]), "+f"(c[2]), "+f"(c[3])
        : "r"(a[0]), "r"(a[1]), "r"(a[2]), "r"(a[3]), "r"(b[0]), "r"(b[1]));
}
__device__ __forceinline__ uint32_t pack_f16(float hi, float lo) {
    uint32_t r;
    asm("cvt.rn.f16x2.f32 %0, %1, %2;" : "=r"(r) : "f"(hi), "f"(lo));
    return r;
}

// ---------------------------------------------------------------------------
// single merged conversion kernel: x -> fp16 hi/lo; wq/wk/wv/wo -> fp16
// flat float4 index space: [x | wq | wk | wv | wo]
// ---------------------------------------------------------------------------
#define N4_X   (T_SEQ * DIM / 4)
#define N4_WQ  (DIM * DIM / 4)
#define N4_WK  (KV_DIM * DIM / 4)
#define N4_WV  (KV_DIM * DIM / 4)
#define N4_WO  (DIM * DIM / 4)
#define N4_TOT (N4_X + N4_WQ + N4_WK + N4_WV + N4_WO)

__global__ __launch_bounds__(256) void cvt_all(
    const float* __restrict__ x,  const float* __restrict__ wq,
    const float* __restrict__ wk, const float* __restrict__ wv,
    const float* __restrict__ wo,
    __half* __restrict__ xh, __half* __restrict__ xl,
    __half* __restrict__ wqh, __half* __restrict__ wkh,
    __half* __restrict__ wvh, __half* __restrict__ woh) {
    int i = blockIdx.x * 256 + threadIdx.x;
    if (i >= N4_TOT) return;
    if (i < N4_X) {
        float4 v = ((const float4*)x)[i];
        __half h0 = __float2half(v.x), h1 = __float2half(v.y);
        __half h2 = __float2half(v.z), h3 = __float2half(v.w);
        ((__half2*)xh)[2 * i]     = __halves2half2(h0, h1);
        ((__half2*)xh)[2 * i + 1] = __halves2half2(h2, h3);
        ((__half2*)xl)[2 * i]     = __halves2half2(
            __float2half(v.x - __half2float(h0)), __float2half(v.y - __half2float(h1)));
        ((__half2*)xl)[2 * i + 1] = __halves2half2(
            __float2half(v.z - __half2float(h2)), __float2half(v.w - __half2float(h3)));
        return;
    }
    const float* src;
    __half* dst;
    int j = i - N4_X;
    if (j < N4_WQ)                          { src = wq; dst = wqh; }
    else if ((j -= N4_WQ) < N4_WK)          { src = wk; dst = wkh; }
    else if ((j -= N4_WK) < N4_WV)          { src = wv; dst = wvh; }
    else { j -= N4_WV;                        src = wo; dst = woh; }
    float4 v = ((const float4*)src)[j];
    ((__half2*)dst)[2 * j]     = __halves2half2(__float2half(v.x), __float2half(v.y));
    ((__half2*)dst)[2 * j + 1] = __halves2half2(__float2half(v.z), __float2half(v.w));
}

// ---------------------------------------------------------------------------
// fp16 2-chain GEMM (K=4096 fixed), two modes:
//   mode 0: C[row*4096+col] = fp32 result                  (O projection)
//   mode 1: fused QKV epilogue — rope+hi/lo split (Q,K), transpose+fp16 (V)
// CTA 128x128, BK=32, 4 warps, chain-pass ordering, cp.async double buffer.
// ---------------------------------------------------------------------------
#define ROWP 80
#define TILEB (128 * ROWP)        // 10240
#define STAGEB (3 * TILEB)        // 30720 (Ah, Al, Bh)
#define EPIPITCH 134              // fp32 staging pitch (floats)
#define GEMM_SMEM (128 * EPIPITCH * 4)   // 68608 >= 2*STAGEB
#define GK 4096
#define GNC 128

__global__ __launch_bounds__(128, 2) void gemm_fused(
    const __half* __restrict__ Ah, const __half* __restrict__ Al,
    const __half* __restrict__ B0, const __half* __restrict__ B1,
    const __half* __restrict__ B2,
    float* __restrict__ C, int mode,
    const float* __restrict__ cs, const float* __restrict__ sn,
    const int* __restrict__ spp,
    __half* __restrict__ qbh, __half* __restrict__ qbl,
    __half* __restrict__ kbh, __half* __restrict__ kbl,
    __half* __restrict__ vt) {
    extern __shared__ char smem[];
    const uint32_t sb = smem_u32(smem);
    const int tid = threadIdx.x, warp = tid >> 5, lane = tid & 31;
    const int wm = (warp >> 1) * 64, wn = (warp & 1) * 64;
    const int m0 = blockIdx.y << 7;
    const int ntg = blockIdx.x;

    // resolve B source + its row base
    const __half* Bsrc;
    int brow0;
    if (mode == 0)      { Bsrc = B0; brow0 = ntg << 7; }
    else if (ntg < 32)  { Bsrc = B0; brow0 = ntg << 7; }
    else if (ntg < 40)  { Bsrc = B1; brow0 = (ntg - 32) << 7; }
    else                { Bsrc = B2; brow0 = (ntg - 40) << 7; }

    float acc[4][8][4];
    #pragma unroll
    for (int mt = 0; mt < 4; mt++)
        #pragma unroll
        for (int nt = 0; nt < 8; nt++)
            #pragma unroll
            for (int j = 0; j < 4; j++) acc[mt][nt][j] = 0.f;

    auto load_stage = [&](int kofs, int s) {
        const uint32_t base = sb + s * STAGEB;
        #pragma unroll
        for (int t = 0; t < 3; t++) {
            const __half* src = (t == 0) ? Ah : (t == 1) ? Al : Bsrc;
            const int rb = (t < 2) ? m0 : brow0;
            #pragma unroll
            for (int i = 0; i < 4; i++) {
                int idx = tid + (i << 7);
                int r = idx >> 2, c = idx & 3;
                uint32_t d = base + t * TILEB + r * ROWP + (c << 4);
                const void* g = src + (size_t)(rb + r) * GK + kofs + (c << 3);
                CP_ASYNC16(d, g);
            }
        }
    };

    load_stage(0, 0);
    CP_COMMIT();
    load_stage(32, 1);
    CP_COMMIT();

    const uint32_t aoffA = (uint32_t)(lane & 15) * ROWP + ((lane >> 4) << 4);
    const uint32_t aoffB = (uint32_t)(((lane >> 4) << 3) + (lane & 7)) * ROWP + (((lane >> 3) & 1) << 4);

    for (int c = 0; c < GNC; c++) {
        const int s = c & 1;
        CP_WAIT1();
        __syncthreads();
        const uint32_t st = sb + s * STAGEB;
        const uint32_t baseA = st + (uint32_t)wm * ROWP + aoffA;
        const uint32_t baseB = st + 2 * TILEB + (uint32_t)wn * ROWP + aoffB;

        #pragma unroll
        for (int ks = 0; ks < 2; ks++) {
            const uint32_t kb = ks << 5;
            uint32_t ah[4][4], al[4][4], bh[8][2];
            #pragma unroll
            for (int mt = 0; mt < 4; mt++) {
                uint32_t a = baseA + (uint32_t)(mt * 16) * ROWP + kb;
                LDSM_X4(ah[mt][0], ah[mt][1], ah[mt][2], ah[mt][3], a);
                LDSM_X4(al[mt][0], al[mt][1], al[mt][2], al[mt][3], a + TILEB);
            }
            #pragma unroll
            for (int np = 0; np < 4; np++) {
                uint32_t b = baseB + (uint32_t)(np * 16) * ROWP + kb;
                LDSM_X4(bh[2 * np][0], bh[2 * np][1], bh[2 * np + 1][0], bh[2 * np + 1][1], b);
            }
            #pragma unroll
            for (int nt = 0; nt < 8; nt++)
                #pragma unroll
                for (int mt = 0; mt < 4; mt++) mma16816f16(acc[mt][nt], ah[mt], bh[nt]);
            #pragma unroll
            for (int nt = 0; nt < 8; nt++)
                #pragma unroll
                for (int mt = 0; mt < 4; mt++) mma16816f16(acc[mt][nt], al[mt], bh[nt]);
        }
        __syncthreads();
        if (c + 2 < GNC) load_stage((c + 2) << 5, s);
        CP_COMMIT();
    }

    const int g4 = lane >> 2, t4 = lane & 3;

    if (mode == 0) {
        // plain fp32 store (O projection)
        #pragma unroll
        for (int mt = 0; mt < 4; mt++) {
            const int row = m0 + wm + (mt << 4) + g4;
            #pragma unroll
            for (int nt = 0; nt < 8; nt++) {
                const int col = (ntg << 7) + wn + (nt << 3) + (t4 << 1);
                *(float2*)&C[(size_t)row * DIM + col]       = make_float2(acc[mt][nt][0], acc[mt][nt][1]);
                *(float2*)&C[(size_t)(row + 8) * DIM + col] = make_float2(acc[mt][nt][2], acc[mt][nt][3]);
            }
        }
        return;
    }

    // ---- mode 1: stage fp32 tile in smem, fused epilogue ----
    __syncthreads();                  // all warps done reading stage buffers
    float* sf = (float*)smem;
    #pragma unroll
    for (int mt = 0; mt < 4; mt++) {
        const int r0 = wm + (mt << 4) + g4;
        #pragma unroll
        for (int nt = 0; nt < 8; nt++) {
            const int cl = wn + (nt << 3) + (t4 << 1);
            *(float2*)&sf[r0 * EPIPITCH + cl]       = make_float2(acc[mt][nt][0], acc[mt][nt][1]);
            *(float2*)&sf[(r0 + 8) * EPIPITCH + cl] = make_float2(acc[mt][nt][2], acc[mt][nt][3]);
        }
    }
    __syncthreads();

    if (ntg < 40) {
        // Q or K: rope + fp16 hi/lo split, coalesced over d = tid
        const bool isQ = (ntg < 32);
        const int sp = *spp;
        const int d = tid;
        const int dd = d & 63;
        const bool hi = d >= 64;
        const float qscale = 0.08838834764831845f;   // 1/sqrt(128)
        __half* dh = isQ ? qbh : kbh;
        __half* dl = isQ ? qbl : kbl;
        const size_t cstride = isQ ? DIM : KV_DIM;
        const size_t cbase = isQ ? (size_t)(ntg << 7) : (size_t)((ntg - 32) << 7);
        for (int r = 0; r < 128; r++) {
            const int t = m0 + r;
            float cv = cs[(size_t)(sp + t) * 64 + dd];
            float sv = sn[(size_t)(sp + t) * 64 + dd];
            float xa = sf[r * EPIPITCH + d];
            float xb = sf[r * EPIPITCH + (d ^ 64)];
            float yv = hi ? (xa * cv + xb * sv) : (xa * cv - xb * sv);
            if (isQ) yv *= qscale;
            __half hh = __float2half(yv);
            __half ll = __float2half(yv - __half2float(hh));
            size_t e = (size_t)t * cstride + cbase + d;
            dh[e] = hh;
            dl[e] = ll;
        }
    } else {
        // V: transpose + fp16, coalesced over t = tid
        const int kvh = ntg - 40;
        #pragma unroll 4
        for (int d = 0; d < 128; d++) {
            float v = sf[tid * EPIPITCH + d];
            vt[(size_t)(kvh * HD + d) * T_SEQ + m0 + tid] = __float2half(v);
        }
    }
}

// ---------------------------------------------------------------------------
// Tensor-core causal GQA flash attention (unchanged from round 6).
// QK^T: fp16 hi/lo 3-chain. P*V: fp16 single-chain. Emits fp16 hi/lo y.
// ---------------------------------------------------------------------------
#define BK 64
#define KP 272
#define VP 144
#define KST 17408
#define VOFF 34816
#define STG 53248
#define ATTN_SMEM (2 * STG)

__global__ __launch_bounds__(256, 1) void attn_tc(
    const __half* __restrict__ qbh, const __half* __restrict__ qbl,
    const __half* __restrict__ kbh, const __half* __restrict__ kbl,
    const __half* __restrict__ vt,
    __half* __restrict__ yh, __half* __restrict__ yl) {
    extern __shared__ char smem[];
    const uint32_t sb = smem_u32(smem);
    const int qt = gridDim.x - 1 - blockIdx.x;
    const int h = blockIdx.y, kvh = h >> 2;
    const int tid = threadIdx.x, warp = tid >> 5, lane = tid & 31;
    const int g4 = lane >> 2, t4 = lane & 3;
    const int wr0 = qt * 128 + warp * 16;
    const int ntiles = 2 * qt + 2;

    uint32_t qfh[8][4], qfl[8][4];
    {
        const uint32_t* ph = (const uint32_t*)qbh;
        const uint32_t* pl = (const uint32_t*)qbl;
        #pragma unroll
        for (int ks = 0; ks < 8; ks++)
            #pragma unroll
            for (int j = 0; j < 4; j++) {
                int row = wr0 + g4 + (j & 1) * 8;
                int col = 16 * ks + 2 * t4 + (j >> 1) * 8;
                size_t e = ((size_t)row * DIM + h * HD + col) >> 1;
                qfh[ks][j] = ph[e];
                qfl[ks][j] = pl[e];
            }
    }

    auto load_stage = [&](int kt, int s) {
        const uint32_t base = sb + s * STG;
        const int kbase = kt * BK;
        #pragma unroll
        for (int i = 0; i < 8; i++) {
            int idx = tid + (i << 8);
            int hl = idx >> 10;
            int w = idx & 1023;
            int row = w >> 4, ch = w & 15;
            const __half* src = (hl ? kbl : kbh) + (size_t)(kbase + row) * KV_DIM + kvh * HD + ch * 8;
            CP_ASYNC16(base + hl * KST + row * KP + ch * 16, src);
        }
        #pragma unroll
        for (int i = 0; i < 4; i++) {
            int idx = tid + (i << 8);
            int row = idx >> 3, ch = idx & 7;
            const __half* src = vt + (size_t)(kvh * HD + row) * T_SEQ + kbase + ch * 8;
            CP_ASYNC16(base + VOFF + row * VP + ch * 16, src);
        }
    };

    float O[16][4];
    #pragma unroll
    for (int nt = 0; nt < 16; nt++)
        #pragma unroll
        for (int j = 0; j < 4; j++) O[nt][j] = 0.f;
    float m0 = -1e30f, m1 = -1e30f, l0 = 0.f, l1 = 0.f;

    load_stage(0, 0); CP_COMMIT();
    load_stage(1, 1); CP_COMMIT();

    for (int kt = 0; kt < ntiles; kt++) {
        CP_WAIT1();
        __syncthreads();
        const uint32_t stp = sb + (kt & 1) * STG;
        const int kbase = kt * BK;

        float S[8][4];
        #pragma unroll
        for (int nt = 0; nt < 8; nt++)
            #pragma unroll
            for (int j = 0; j < 4; j++) S[nt][j] = 0.f;
        #pragma unroll
        for (int ks = 0; ks < 8; ks++) {
            #pragma unroll
            for (int nt = 0; nt < 8; nt++) {
                uint32_t a0 = stp + (uint32_t)(nt * 8 + g4) * KP + (16 * ks + 2 * t4) * 2;
                uint32_t bh[2], bl[2];
                LDS32(bh[0], a0);        LDS32(bh[1], a0 + 16);
                LDS32(bl[0], a0 + KST);  LDS32(bl[1], a0 + KST + 16);
                mma16816f16(S[nt], qfh[ks], bh);
                mma16816f16(S[nt], qfl[ks], bh);
                mma16816f16(S[nt], qfh[ks], bl);
            }
        }

        if (kbase + BK - 1 > wr0) {
            #pragma unroll
            for (int nt = 0; nt < 8; nt++) {
                int col = kbase + nt * 8 + 2 * t4;
                int rl = wr0 + g4, rh = wr0 + 8 + g4;
                if (col     > rl) S[nt][0] = -1e30f;
                if (col + 1 > rl) S[nt][1] = -1e30f;
                if (col     > rh) S[nt][2] = -1e30f;
                if (col + 1 > rh) S[nt][3] = -1e30f;
            }
        }

        float mx0 = -1e30f, mx1 = -1e30f;
        #pragma unroll
        for (int nt = 0; nt < 8; nt++) {
            mx0 = fmaxf(mx0, fmaxf(S[nt][0], S[nt][1]));
            mx1 = fmaxf(mx1, fmaxf(S[nt][2], S[nt][3]));
        }
        mx0 = fmaxf(mx0, __shfl_xor_sync(0xffffffffu, mx0, 1));
        mx0 = fmaxf(mx0, __shfl_xor_sync(0xffffffffu, mx0, 2));
        mx1 = fmaxf(mx1, __shfl_xor_sync(0xffffffffu, mx1, 1));
        mx1 = fmaxf(mx1, __shfl_xor_sync(0xffffffffu, mx1, 2));
        float mn0 = fmaxf(m0, mx0), mn1 = fmaxf(m1, mx1);
        float a0 = __expf(m0 - mn0), a1 = __expf(m1 - mn1);
        m0 = mn0; m1 = mn1;
        float ts0 = 0.f, ts1 = 0.f;
        #pragma unroll
        for (int nt = 0; nt < 8; nt++) {
            S[nt][0] = __expf(S[nt][0] - mn0);
            S[nt][1] = __expf(S[nt][1] - mn0);
            S[nt][2] = __expf(S[nt][2] - mn1);
            S[nt][3] = __expf(S[nt][3] - mn1);
            ts0 += S[nt][0] + S[nt][1];
            ts1 += S[nt][2] + S[nt][3];
        }
        ts0 += __shfl_xor_sync(0xffffffffu, ts0, 1);
        ts0 += __shfl_xor_sync(0xffffffffu, ts0, 2);
        ts1 += __shfl_xor_sync(0xffffffffu, ts1, 1);
        ts1 += __shfl_xor_sync(0xffffffffu, ts1, 2);
        l0 = l0 * a0 + ts0;
        l1 = l1 * a1 + ts1;
        #pragma unroll
        for (int nt = 0; nt < 16; nt++) {
            O[nt][0] *= a0; O[nt][1] *= a0;
            O[nt][2] *= a1; O[nt][3] *= a1;
        }

        uint32_t pk[4][4];
        #pragma unroll
        for (int ks = 0; ks < 4; ks++) {
            pk[ks][0] = pack_f16(S[2 * ks][1],     S[2 * ks][0]);
            pk[ks][1] = pack_f16(S[2 * ks][3],     S[2 * ks][2]);
            pk[ks][2] = pack_f16(S[2 * ks + 1][1], S[2 * ks + 1][0]);
            pk[ks][3] = pack_f16(S[2 * ks + 1][3], S[2 * ks + 1][2]);
        }

        #pragma unroll
        for (int ks = 0; ks < 4; ks++) {
            #pragma unroll
            for (int nt = 0; nt < 16; nt++) {
                uint32_t a0 = stp + VOFF + (uint32_t)(nt * 8 + g4) * VP + (16 * ks + 2 * t4) * 2;
                uint32_t b[2];
                LDS32(b[0], a0);
                LDS32(b[1], a0 + 16);
                mma16816f16(O[nt], pk[ks], b);
            }
        }

        __syncthreads();
        if (kt + 2 < ntiles) load_stage(kt + 2, kt & 1);
        CP_COMMIT();
    }

    float i0 = 1.f / l0, i1 = 1.f / l1;
    #pragma unroll
    for (int nt = 0; nt < 16; nt++) {
        int col = h * HD + nt * 8 + 2 * t4;
        size_t e0 = (size_t)(wr0 + g4) * DIM + col;
        size_t e1 = (size_t)(wr0 + 8 + g4) * DIM + col;
        float v00 = O[nt][0] * i0, v01 = O[nt][1] * i0;
        float v10 = O[nt][2] * i1, v11 = O[nt][3] * i1;
        __half h00 = __float2half(v00), h01 = __float2half(v01);
        __half h10 = __float2half(v10), h11 = __float2half(v11);
        *(__half2*)(yh + e0) = __halves2half2(h00, h01);
        *(__half2*)(yh + e1) = __halves2half2(h10, h11);
        *(__half2*)(yl + e0) = __halves2half2(
            __float2half(v00 - __half2float(h00)), __float2half(v01 - __half2float(h01)));
        *(__half2*)(yl + e1) = __halves2half2(
            __float2half(v10 - __half2float(h10)), __float2half(v11 - __half2float(h11)));
    }
}

// ---------------------------------------------------------------------------
extern "C" void kernel_launch(void* const* d_in, const int* in_sizes, int n_in,
                              void* d_out, int out_size) {
    const float* x  = (const float*)d_in[0];
    const float* cs = (const float*)d_in[1];
    const float* sn = (const float*)d_in[2];
    const float* wq = (const float*)d_in[3];
    const float* wk = (const float*)d_in[4];
    const float* wv = (const float*)d_in[5];
    const float* wo = (const float*)d_in[6];
    const int*   sp = (const int*)d_in[7];
    float* out = (float*)d_out;

    __half *xh, *xl, *yh, *yl, *wqh, *wkh, *wvh, *woh;
    __half *qbh, *qbl, *kbh, *kbl, *vt;
    cudaGetSymbolAddress((void**)&xh, g_xh);   cudaGetSymbolAddress((void**)&xl, g_xl);
    cudaGetSymbolAddress((void**)&yh, g_yh);   cudaGetSymbolAddress((void**)&yl, g_yl);
    cudaGetSymbolAddress((void**)&wqh, g_wqh); cudaGetSymbolAddress((void**)&wkh, g_wkh);
    cudaGetSymbolAddress((void**)&wvh, g_wvh); cudaGetSymbolAddress((void**)&woh, g_woh);
    cudaGetSymbolAddress((void**)&qbh, g_qbh); cudaGetSymbolAddress((void**)&qbl, g_qbl);
    cudaGetSymbolAddress((void**)&kbh, g_kbh); cudaGetSymbolAddress((void**)&kbl, g_kbl);
    cudaGetSymbolAddress((void**)&vt, g_vt);

    cudaFuncSetAttribute(gemm_fused, cudaFuncAttributeMaxDynamicSharedMemorySize, GEMM_SMEM);
    cudaFuncSetAttribute(attn_tc, cudaFuncAttributeMaxDynamicSharedMemorySize, ATTN_SMEM);

    // 1) all input conversions, one launch
    cvt_all<<<(N4_TOT + 255) / 256, 256>>>(x, wq, wk, wv, wo,
                                           xh, xl, wqh, wkh, wvh, woh);
    // 2) fused QKV projection + rope + split + V-transpose, one launch
    gemm_fused<<<dim3(48, T_SEQ / 128), 128, GEMM_SMEM>>>(
        xh, xl, wqh, wkh, wvh, nullptr, 1,
        cs, sn, sp, qbh, qbl, kbh, kbl, vt);
    // 3) tensor-core flash attention
    attn_tc<<<dim3(T_SEQ / 128, NH), 256, ATTN_SMEM>>>(qbh, qbl, kbh, kbl, vt, yh, yl);
    // 4) output projection
    gemm_fused<<<dim3(32, T_SEQ / 128), 128, GEMM_SMEM>>>(
        yh, yl, woh, nullptr, nullptr, out, 0,
        nullptr, nullptr, nullptr, nullptr, nullptr, nullptr, nullptr, nullptr);
}

// round 8
// speedup vs baseline: 4.5911x; 1.0240x over previous
#include <cuda_runtime.h>
#include <cuda_bf16.h>
#include <cuda_fp16.h>
#include <cstdint>

#define T_SEQ 2048
#define DIM 4096
#define KV_DIM 1024
#define NH 32
#define NKV 8
#define HD 128

// ---------------- scratch (__device__ globals; allocation-free rule) --------
__device__ __align__(16) __half g_xh[T_SEQ * DIM];
__device__ __align__(16) __half g_xl[T_SEQ * DIM];
__device__ __align__(16) __half g_yh[T_SEQ * DIM];
__device__ __align__(16) __half g_yl[T_SEQ * DIM];
__device__ __align__(16) __half g_wqh[DIM * DIM];
__device__ __align__(16) __half g_wkh[KV_DIM * DIM];
__device__ __align__(16) __half g_wvh[KV_DIM * DIM];
__device__ __align__(16) __half g_woh[DIM * DIM];
// attention operands (fp16 hi/lo)
__device__ __align__(16) __half g_qbh[T_SEQ * DIM];
__device__ __align__(16) __half g_qbl[T_SEQ * DIM];
__device__ __align__(16) __half g_kbh[T_SEQ * KV_DIM];
__device__ __align__(16) __half g_kbl[T_SEQ * KV_DIM];
__device__ __align__(16) __half g_vt[NKV * HD * T_SEQ];   // [kvh][hd][t]

// ---------------- portable PTX helpers (sm_80+ features only) ---------------
__device__ __forceinline__ uint32_t smem_u32(const void* p) {
    uint32_t a;
    asm("{ .reg .u64 t; cvta.to.shared.u64 t, %1; cvt.u32.u64 %0, t; }" : "=r"(a) : "l"(p));
    return a;
}
#define CP_ASYNC16(dst, src) \
    asm volatile("cp.async.cg.shared.global [%0], [%1], 16;" :: "r"(dst), "l"(src) : "memory")
#define CP_COMMIT() asm volatile("cp.async.commit_group;" ::: "memory")
#define CP_WAIT1()  asm volatile("cp.async.wait_group 1;" ::: "memory")
#define CP_WAIT2()  asm volatile("cp.async.wait_group 2;" ::: "memory")
#define LDS32(v, addr) asm volatile("ld.shared.b32 %0, [%1];" : "=r"(v) : "r"(addr))
#define LDSM_X4(r0, r1, r2, r3, addr) \
    asm volatile("ldmatrix.sync.aligned.m8n8.x4.shared.b16 {%0,%1,%2,%3}, [%4];" \
        : "=r"(r0), "=r"(r1), "=r"(r2), "=r"(r3) : "r"(addr))

__device__ __forceinline__ void mma16816f16(float* c, const uint32_t* a, const uint32_t* b) {
    asm volatile(
        "mma.sync.aligned.m16n8k16.row.col.f32.f16.f16.f32 "
        "{%0,%1,%2,%3}, {%4,%5,%6,%7}, {%8,%9}, {%0,%1,%2,%3};"
        : "+f"(c[0]), "+f"(c[1]), "+f"(c[2]), "+f"(c[3])
        : "r"(a[0]), "r"(a[1]), "r"(a[2]), "r"(a[3]), "r"(b[0]), "r"(b[1]));
}
__device__ __forceinline__ uint32_t pack_f16(float hi, float lo) {
    uint32_t r;
    asm("cvt.rn.f16x2.f32 %0, %1, %2;" : "=r"(r) : "f"(hi), "f"(lo));
    return r;
}

// ---------------------------------------------------------------------------
// merged conversion kernel: x -> fp16 hi/lo; wq/wk/wv/wo -> fp16
// ---------------------------------------------------------------------------
#define N4_X   (T_SEQ * DIM / 4)
#define N4_WQ  (DIM * DIM / 4)
#define N4_WK  (KV_DIM * DIM / 4)
#define N4_WV  (KV_DIM * DIM / 4)
#define N4_WO  (DIM * DIM / 4)
#define N4_TOT (N4_X + N4_WQ + N4_WK + N4_WV + N4_WO)

__global__ __launch_bounds__(256) void cvt_all(
    const float* __restrict__ x,  const float* __restrict__ wq,
    const float* __restrict__ wk, const float* __restrict__ wv,
    const float* __restrict__ wo,
    __half* __restrict__ xh, __half* __restrict__ xl,
    __half* __restrict__ wqh, __half* __restrict__ wkh,
    __half* __restrict__ wvh, __half* __restrict__ woh) {
    int i = blockIdx.x * 256 + threadIdx.x;
    if (i >= N4_TOT) return;
    if (i < N4_X) {
        float4 v = ((const float4*)x)[i];
        __half h0 = __float2half(v.x), h1 = __float2half(v.y);
        __half h2 = __float2half(v.z), h3 = __float2half(v.w);
        ((__half2*)xh)[2 * i]     = __halves2half2(h0, h1);
        ((__half2*)xh)[2 * i + 1] = __halves2half2(h2, h3);
        ((__half2*)xl)[2 * i]     = __halves2half2(
            __float2half(v.x - __half2float(h0)), __float2half(v.y - __half2float(h1)));
        ((__half2*)xl)[2 * i + 1] = __halves2half2(
            __float2half(v.z - __half2float(h2)), __float2half(v.w - __half2float(h3)));
        return;
    }
    const float* src;
    __half* dst;
    int j = i - N4_X;
    if (j < N4_WQ)                          { src = wq; dst = wqh; }
    else if ((j -= N4_WQ) < N4_WK)          { src = wk; dst = wkh; }
    else if ((j -= N4_WK) < N4_WV)          { src = wv; dst = wvh; }
    else { j -= N4_WV;                        src = wo; dst = woh; }
    float4 v = ((const float4*)src)[j];
    ((__half2*)dst)[2 * j]     = __halves2half2(__float2half(v.x), __float2half(v.y));
    ((__half2*)dst)[2 * j + 1] = __halves2half2(__float2half(v.z), __float2half(v.w));
}

// ---------------------------------------------------------------------------
// fp16 2-chain GEMM v3: 256 threads, warp tile 32x64 (8 warps = 4/SMSP after
// 2-CTA residency), 3-stage cp.async pipeline. K=4096 fixed. Two modes:
//   mode 0: fp32 store (O projection)
//   mode 1: fused QKV epilogue (rope + hi/lo split for Q,K; transpose V)
// ---------------------------------------------------------------------------
#define ROWP 80
#define TILEB (128 * ROWP)        // 10240
#define STAGEB (3 * TILEB)        // 30720 (Ah, Al, Bh)
#define NSTAGE 3
#define EPIPITCH 134
#define GEMM_SMEM (NSTAGE * STAGEB)      // 92160 >= 128*134*4 = 68608
#define GK 4096
#define GNC 128

__global__ __launch_bounds__(256, 2) void gemm_fused(
    const __half* __restrict__ Ah, const __half* __restrict__ Al,
    const __half* __restrict__ B0, const __half* __restrict__ B1,
    const __half* __restrict__ B2,
    float* __restrict__ C, int mode,
    const float* __restrict__ cs, const float* __restrict__ sn,
    const int* __restrict__ spp,
    __half* __restrict__ qbh, __half* __restrict__ qbl,
    __half* __restrict__ kbh, __half* __restrict__ kbl,
    __half* __restrict__ vt) {
    extern __shared__ char smem[];
    const uint32_t sb = smem_u32(smem);
    const int tid = threadIdx.x, warp = tid >> 5, lane = tid & 31;
    const int wm = (warp & 3) << 5;            // 0,32,64,96
    const int wn = (warp >> 2) << 6;           // 0,64
    const int m0 = blockIdx.y << 7;
    const int ntg = blockIdx.x;

    const __half* Bsrc;
    int brow0;
    if (mode == 0)      { Bsrc = B0; brow0 = ntg << 7; }
    else if (ntg < 32)  { Bsrc = B0; brow0 = ntg << 7; }
    else if (ntg < 40)  { Bsrc = B1; brow0 = (ntg - 32) << 7; }
    else                { Bsrc = B2; brow0 = (ntg - 40) << 7; }

    float acc[2][8][4];
    #pragma unroll
    for (int mt = 0; mt < 2; mt++)
        #pragma unroll
        for (int nt = 0; nt < 8; nt++)
            #pragma unroll
            for (int j = 0; j < 4; j++) acc[mt][nt][j] = 0.f;

    auto load_stage = [&](int kofs, int s) {
        const uint32_t base = sb + s * STAGEB;
        #pragma unroll
        for (int t = 0; t < 3; t++) {
            const __half* src = (t == 0) ? Ah : (t == 1) ? Al : Bsrc;
            const int rb = (t < 2) ? m0 : brow0;
            #pragma unroll
            for (int i = 0; i < 2; i++) {
                int idx = tid + (i << 8);
                int r = idx >> 2, c = idx & 3;
                uint32_t d = base + t * TILEB + r * ROWP + (c << 4);
                const void* g = src + (size_t)(rb + r) * GK + kofs + (c << 3);
                CP_ASYNC16(d, g);
            }
        }
    };

    load_stage(0, 0);  CP_COMMIT();
    load_stage(32, 1); CP_COMMIT();
    load_stage(64, 2); CP_COMMIT();

    const uint32_t aoffA = (uint32_t)(lane & 15) * ROWP + ((lane >> 4) << 4);
    const uint32_t aoffB = (uint32_t)(((lane >> 4) << 3) + (lane & 7)) * ROWP + (((lane >> 3) & 1) << 4);

    int s = 0;
    for (int c = 0; c < GNC; c++) {
        CP_WAIT2();
        __syncthreads();
        const uint32_t st = sb + s * STAGEB;
        const uint32_t baseA = st + (uint32_t)wm * ROWP + aoffA;
        const uint32_t baseB = st + 2 * TILEB + (uint32_t)wn * ROWP + aoffB;

        #pragma unroll
        for (int ks = 0; ks < 2; ks++) {
            const uint32_t kb = ks << 5;
            uint32_t ah[2][4], al[2][4], bh[8][2];
            #pragma unroll
            for (int mt = 0; mt < 2; mt++) {
                uint32_t a = baseA + (uint32_t)(mt << 4) * ROWP + kb;
                LDSM_X4(ah[mt][0], ah[mt][1], ah[mt][2], ah[mt][3], a);
                LDSM_X4(al[mt][0], al[mt][1], al[mt][2], al[mt][3], a + TILEB);
            }
            #pragma unroll
            for (int np = 0; np < 4; np++) {
                uint32_t b = baseB + (uint32_t)(np << 4) * ROWP + kb;
                LDSM_X4(bh[2 * np][0], bh[2 * np][1], bh[2 * np + 1][0], bh[2 * np + 1][1], b);
            }
            #pragma unroll
            for (int nt = 0; nt < 8; nt++)
                #pragma unroll
                for (int mt = 0; mt < 2; mt++) mma16816f16(acc[mt][nt], ah[mt], bh[nt]);
            #pragma unroll
            for (int nt = 0; nt < 8; nt++)
                #pragma unroll
                for (int mt = 0; mt < 2; mt++) mma16816f16(acc[mt][nt], al[mt], bh[nt]);
        }
        __syncthreads();
        if (c + 3 < GNC) load_stage((c + 3) << 5, s);
        CP_COMMIT();
        s = (s == 2) ? 0 : s + 1;
    }

    const int g4 = lane >> 2, t4 = lane & 3;

    if (mode == 0) {
        #pragma unroll
        for (int mt = 0; mt < 2; mt++) {
            const int row = m0 + wm + (mt << 4) + g4;
            #pragma unroll
            for (int nt = 0; nt < 8; nt++) {
                const int col = (ntg << 7) + wn + (nt << 3) + (t4 << 1);
                *(float2*)&C[(size_t)row * DIM + col]       = make_float2(acc[mt][nt][0], acc[mt][nt][1]);
                *(float2*)&C[(size_t)(row + 8) * DIM + col] = make_float2(acc[mt][nt][2], acc[mt][nt][3]);
            }
        }
        return;
    }

    // ---- mode 1: stage fp32 tile in smem, fused epilogue ----
    __syncthreads();
    float* sf = (float*)smem;
    #pragma unroll
    for (int mt = 0; mt < 2; mt++) {
        const int r0 = wm + (mt << 4) + g4;
        #pragma unroll
        for (int nt = 0; nt < 8; nt++) {
            const int cl = wn + (nt << 3) + (t4 << 1);
            *(float2*)&sf[r0 * EPIPITCH + cl]       = make_float2(acc[mt][nt][0], acc[mt][nt][1]);
            *(float2*)&sf[(r0 + 8) * EPIPITCH + cl] = make_float2(acc[mt][nt][2], acc[mt][nt][3]);
        }
    }
    __syncthreads();

    if (ntg < 40) {
        // Q or K: rope + fp16 hi/lo split; 256 threads = (2 row-halves) x 128 d
        const bool isQ = (ntg < 32);
        const int sp = *spp;
        const int d = tid & 127;
        const int dd = d & 63;
        const bool hi = d >= 64;
        const int r0 = (tid >> 7) << 6;            // 0 or 64
        const float qscale = 0.08838834764831845f;
        __half* dh = isQ ? qbh : kbh;
        __half* dl = isQ ? qbl : kbl;
        const size_t cstride = isQ ? DIM : KV_DIM;
        const size_t cbase = isQ ? (size_t)(ntg << 7) : (size_t)((ntg - 32) << 7);
        for (int r = r0; r < r0 + 64; r++) {
            const int t = m0 + r;
            float cv = cs[(size_t)(sp + t) * 64 + dd];
            float sv = sn[(size_t)(sp + t) * 64 + dd];
            float xa = sf[r * EPIPITCH + d];
            float xb = sf[r * EPIPITCH + (d ^ 64)];
            float yv = hi ? (xa * cv + xb * sv) : (xa * cv - xb * sv);
            if (isQ) yv *= qscale;
            __half hh = __float2half(yv);
            __half ll = __float2half(yv - __half2float(hh));
            size_t e = (size_t)t * cstride + cbase + d;
            dh[e] = hh;
            dl[e] = ll;
        }
    } else {
        // V: transpose + fp16; 256 threads = 128 t x (2 d-halves)
        const int kvh = ntg - 40;
        const int t = tid & 127;
        const int d0 = (tid >> 7) << 6;            // 0 or 64
        #pragma unroll 4
        for (int d = d0; d < d0 + 64; d++) {
            float v = sf[t * EPIPITCH + d];
            vt[(size_t)(kvh * HD + d) * T_SEQ + m0 + t] = __float2half(v);
        }
    }
}

// ---------------------------------------------------------------------------
// Tensor-core causal GQA flash attention (unchanged — proven at 6.9e-4).
// ---------------------------------------------------------------------------
#define BK 64
#define KP 272
#define VP 144
#define KST 17408
#define VOFF 34816
#define STG 53248
#define ATTN_SMEM (2 * STG)

__global__ __launch_bounds__(256, 1) void attn_tc(
    const __half* __restrict__ qbh, const __half* __restrict__ qbl,
    const __half* __restrict__ kbh, const __half* __restrict__ kbl,
    const __half* __restrict__ vt,
    __half* __restrict__ yh, __half* __restrict__ yl) {
    extern __shared__ char smem[];
    const uint32_t sb = smem_u32(smem);
    const int qt = gridDim.x - 1 - blockIdx.x;
    const int h = blockIdx.y, kvh = h >> 2;
    const int tid = threadIdx.x, warp = tid >> 5, lane = tid & 31;
    const int g4 = lane >> 2, t4 = lane & 3;
    const int wr0 = qt * 128 + warp * 16;
    const int ntiles = 2 * qt + 2;

    uint32_t qfh[8][4], qfl[8][4];
    {
        const uint32_t* ph = (const uint32_t*)qbh;
        const uint32_t* pl = (const uint32_t*)qbl;
        #pragma unroll
        for (int ks = 0; ks < 8; ks++)
            #pragma unroll
            for (int j = 0; j < 4; j++) {
                int row = wr0 + g4 + (j & 1) * 8;
                int col = 16 * ks + 2 * t4 + (j >> 1) * 8;
                size_t e = ((size_t)row * DIM + h * HD + col) >> 1;
                qfh[ks][j] = ph[e];
                qfl[ks][j] = pl[e];
            }
    }

    auto load_stage = [&](int kt, int s) {
        const uint32_t base = sb + s * STG;
        const int kbase = kt * BK;
        #pragma unroll
        for (int i = 0; i < 8; i++) {
            int idx = tid + (i << 8);
            int hl = idx >> 10;
            int w = idx & 1023;
            int row = w >> 4, ch = w & 15;
            const __half* src = (hl ? kbl : kbh) + (size_t)(kbase + row) * KV_DIM + kvh * HD + ch * 8;
            CP_ASYNC16(base + hl * KST + row * KP + ch * 16, src);
        }
        #pragma unroll
        for (int i = 0; i < 4; i++) {
            int idx = tid + (i << 8);
            int row = idx >> 3, ch = idx & 7;
            const __half* src = vt + (size_t)(kvh * HD + row) * T_SEQ + kbase + ch * 8;
            CP_ASYNC16(base + VOFF + row * VP + ch * 16, src);
        }
    };

    float O[16][4];
    #pragma unroll
    for (int nt = 0; nt < 16; nt++)
        #pragma unroll
        for (int j = 0; j < 4; j++) O[nt][j] = 0.f;
    float m0 = -1e30f, m1 = -1e30f, l0 = 0.f, l1 = 0.f;

    load_stage(0, 0); CP_COMMIT();
    load_stage(1, 1); CP_COMMIT();

    for (int kt = 0; kt < ntiles; kt++) {
        CP_WAIT1();
        __syncthreads();
        const uint32_t stp = sb + (kt & 1) * STG;
        const int kbase = kt * BK;

        float S[8][4];
        #pragma unroll
        for (int nt = 0; nt < 8; nt++)
            #pragma unroll
            for (int j = 0; j < 4; j++) S[nt][j] = 0.f;
        #pragma unroll
        for (int ks = 0; ks < 8; ks++) {
            #pragma unroll
            for (int nt = 0; nt < 8; nt++) {
                uint32_t a0 = stp + (uint32_t)(nt * 8 + g4) * KP + (16 * ks + 2 * t4) * 2;
                uint32_t bh[2], bl[2];
                LDS32(bh[0], a0);        LDS32(bh[1], a0 + 16);
                LDS32(bl[0], a0 + KST);  LDS32(bl[1], a0 + KST + 16);
                mma16816f16(S[nt], qfh[ks], bh);
                mma16816f16(S[nt], qfl[ks], bh);
                mma16816f16(S[nt], qfh[ks], bl);
            }
        }

        if (kbase + BK - 1 > wr0) {
            #pragma unroll
            for (int nt = 0; nt < 8; nt++) {
                int col = kbase + nt * 8 + 2 * t4;
                int rl = wr0 + g4, rh = wr0 + 8 + g4;
                if (col     > rl) S[nt][0] = -1e30f;
                if (col + 1 > rl) S[nt][1] = -1e30f;
                if (col     > rh) S[nt][2] = -1e30f;
                if (col + 1 > rh) S[nt][3] = -1e30f;
            }
        }

        float mx0 = -1e30f, mx1 = -1e30f;
        #pragma unroll
        for (int nt = 0; nt < 8; nt++) {
            mx0 = fmaxf(mx0, fmaxf(S[nt][0], S[nt][1]));
            mx1 = fmaxf(mx1, fmaxf(S[nt][2], S[nt][3]));
        }
        mx0 = fmaxf(mx0, __shfl_xor_sync(0xffffffffu, mx0, 1));
        mx0 = fmaxf(mx0, __shfl_xor_sync(0xffffffffu, mx0, 2));
        mx1 = fmaxf(mx1, __shfl_xor_sync(0xffffffffu, mx1, 1));
        mx1 = fmaxf(mx1, __shfl_xor_sync(0xffffffffu, mx1, 2));
        float mn0 = fmaxf(m0, mx0), mn1 = fmaxf(m1, mx1);
        float a0 = __expf(m0 - mn0), a1 = __expf(m1 - mn1);
        m0 = mn0; m1 = mn1;
        float ts0 = 0.f, ts1 = 0.f;
        #pragma unroll
        for (int nt = 0; nt < 8; nt++) {
            S[nt][0] = __expf(S[nt][0] - mn0);
            S[nt][1] = __expf(S[nt][1] - mn0);
            S[nt][2] = __expf(S[nt][2] - mn1);
            S[nt][3] = __expf(S[nt][3] - mn1);
            ts0 += S[nt][0] + S[nt][1];
            ts1 += S[nt][2] + S[nt][3];
        }
        ts0 += __shfl_xor_sync(0xffffffffu, ts0, 1);
        ts0 += __shfl_xor_sync(0xffffffffu, ts0, 2);
        ts1 += __shfl_xor_sync(0xffffffffu, ts1, 1);
        ts1 += __shfl_xor_sync(0xffffffffu, ts1, 2);
        l0 = l0 * a0 + ts0;
        l1 = l1 * a1 + ts1;
        #pragma unroll
        for (int nt = 0; nt < 16; nt++) {
            O[nt][0] *= a0; O[nt][1] *= a0;
            O[nt][2] *= a1; O[nt][3] *= a1;
        }

        uint32_t pk[4][4];
        #pragma unroll
        for (int ks = 0; ks < 4; ks++) {
            pk[ks][0] = pack_f16(S[2 * ks][1],     S[2 * ks][0]);
            pk[ks][1] = pack_f16(S[2 * ks][3],     S[2 * ks][2]);
            pk[ks][2] = pack_f16(S[2 * ks + 1][1], S[2 * ks + 1][0]);
            pk[ks][3] = pack_f16(S[2 * ks + 1][3], S[2 * ks + 1][2]);
        }

        #pragma unroll
        for (int ks = 0; ks < 4; ks++) {
            #pragma unroll
            for (int nt = 0; nt < 16; nt++) {
                uint32_t a0 = stp + VOFF + (uint32_t)(nt * 8 + g4) * VP + (16 * ks + 2 * t4) * 2;
                uint32_t b[2];
                LDS32(b[0], a0);
                LDS32(b[1], a0 + 16);
                mma16816f16(O[nt], pk[ks], b);
            }
        }

        __syncthreads();
        if (kt + 2 < ntiles) load_stage(kt + 2, kt & 1);
        CP_COMMIT();
    }

    float i0 = 1.f / l0, i1 = 1.f / l1;
    #pragma unroll
    for (int nt = 0; nt < 16; nt++) {
        int col = h * HD + nt * 8 + 2 * t4;
        size_t e0 = (size_t)(wr0 + g4) * DIM + col;
        size_t e1 = (size_t)(wr0 + 8 + g4) * DIM + col;
        float v00 = O[nt][0] * i0, v01 = O[nt][1] * i0;
        float v10 = O[nt][2] * i1, v11 = O[nt][3] * i1;
        __half h00 = __float2half(v00), h01 = __float2half(v01);
        __half h10 = __float2half(v10), h11 = __float2half(v11);
        *(__half2*)(yh + e0) = __halves2half2(h00, h01);
        *(__half2*)(yh + e1) = __halves2half2(h10, h11);
        *(__half2*)(yl + e0) = __halves2half2(
            __float2half(v00 - __half2float(h00)), __float2half(v01 - __half2float(h01)));
        *(__half2*)(yl + e1) = __halves2half2(
            __float2half(v10 - __half2float(h10)), __float2half(v11 - __half2float(h11)));
    }
}

// ---------------------------------------------------------------------------
extern "C" void kernel_launch(void* const* d_in, const int* in_sizes, int n_in,
                              void* d_out, int out_size) {
    const float* x  = (const float*)d_in[0];
    const float* cs = (const float*)d_in[1];
    const float* sn = (const float*)d_in[2];
    const float* wq = (const float*)d_in[3];
    const float* wk = (const float*)d_in[4];
    const float* wv = (const float*)d_in[5];
    const float* wo = (const float*)d_in[6];
    const int*   sp = (const int*)d_in[7];
    float* out = (float*)d_out;

    __half *xh, *xl, *yh, *yl, *wqh, *wkh, *wvh, *woh;
    __half *qbh, *qbl, *kbh, *kbl, *vt;
    cudaGetSymbolAddress((void**)&xh, g_xh);   cudaGetSymbolAddress((void**)&xl, g_xl);
    cudaGetSymbolAddress((void**)&yh, g_yh);   cudaGetSymbolAddress((void**)&yl, g_yl);
    cudaGetSymbolAddress((void**)&wqh, g_wqh); cudaGetSymbolAddress((void**)&wkh, g_wkh);
    cudaGetSymbolAddress((void**)&wvh, g_wvh); cudaGetSymbolAddress((void**)&woh, g_woh);
    cudaGetSymbolAddress((void**)&qbh, g_qbh); cudaGetSymbolAddress((void**)&qbl, g_qbl);
    cudaGetSymbolAddress((void**)&kbh, g_kbh); cudaGetSymbolAddress((void**)&kbl, g_kbl);
    cudaGetSymbolAddress((void**)&vt, g_vt);

    cudaFuncSetAttribute(gemm_fused, cudaFuncAttributeMaxDynamicSharedMemorySize, GEMM_SMEM);
    cudaFuncSetAttribute(attn_tc, cudaFuncAttributeMaxDynamicSharedMemorySize, ATTN_SMEM);

    cvt_all<<<(N4_TOT + 255) / 256, 256>>>(x, wq, wk, wv, wo,
                                           xh, xl, wqh, wkh, wvh, woh);
    gemm_fused<<<dim3(48, T_SEQ / 128), 256, GEMM_SMEM>>>(
        xh, xl, wqh, wkh, wvh, nullptr, 1,
        cs, sn, sp, qbh, qbl, kbh, kbl, vt);
    attn_tc<<<dim3(T_SEQ / 128, NH), 256, ATTN_SMEM>>>(qbh, qbl, kbh, kbl, vt, yh, yl);
    gemm_fused<<<dim3(32, T_SEQ / 128), 256, GEMM_SMEM>>>(
        yh, yl, woh, nullptr, nullptr, out, 0,
        nullptr, nullptr, nullptr, nullptr, nullptr, nullptr, nullptr, nullptr);
}

// round 9
// speedup vs baseline: 5.7251x; 1.2470x over previous
#include <cuda_runtime.h>
#include <cuda_bf16.h>
#include <cuda_fp16.h>
#include <cstdint>

#define T_SEQ 2048
#define DIM 4096
#define KV_DIM 1024
#define NH 32
#define NKV 8
#define HD 128

// ---------------- scratch (__device__ globals; allocation-free rule) --------
__device__ __align__(16) __half g_xh[T_SEQ * DIM];
__device__ __align__(16) __half g_xl[T_SEQ * DIM];
__device__ __align__(16) __half g_yh[T_SEQ * DIM];
__device__ __align__(16) __half g_yl[T_SEQ * DIM];
__device__ __align__(16) __half g_wqh[DIM * DIM];
__device__ __align__(16) __half g_wkh[KV_DIM * DIM];
__device__ __align__(16) __half g_wvh[KV_DIM * DIM];
__device__ __align__(16) __half g_woh[DIM * DIM];
// attention operands (fp16 hi/lo)
__device__ __align__(16) __half g_qbh[T_SEQ * DIM];
__device__ __align__(16) __half g_qbl[T_SEQ * DIM];
__device__ __align__(16) __half g_kbh[T_SEQ * KV_DIM];
__device__ __align__(16) __half g_kbl[T_SEQ * KV_DIM];
__device__ __align__(16) __half g_vt[NKV * HD * T_SEQ];   // [kvh][hd][t]

// ---------------- portable PTX helpers (sm_80+ features only) ---------------
__device__ __forceinline__ uint32_t smem_u32(const void* p) {
    uint32_t a;
    asm("{ .reg .u64 t; cvta.to.shared.u64 t, %1; cvt.u32.u64 %0, t; }" : "=r"(a) : "l"(p));
    return a;
}
#define CP_ASYNC16(dst, src) \
    asm volatile("cp.async.cg.shared.global [%0], [%1], 16;" :: "r"(dst), "l"(src) : "memory")
#define CP_COMMIT() asm volatile("cp.async.commit_group;" ::: "memory")
#define CP_WAIT1()  asm volatile("cp.async.wait_group 1;" ::: "memory")
#define CP_WAIT2()  asm volatile("cp.async.wait_group 2;" ::: "memory")
#define CP_WAIT3()  asm volatile("cp.async.wait_group 3;" ::: "memory")
#define LDS32(v, addr) asm volatile("ld.shared.b32 %0, [%1];" : "=r"(v) : "r"(addr))
#define LDSM_X4(r0, r1, r2, r3, addr) \
    asm volatile("ldmatrix.sync.aligned.m8n8.x4.shared.b16 {%0,%1,%2,%3}, [%4];" \
        : "=r"(r0), "=r"(r1), "=r"(r2), "=r"(r3) : "r"(addr))

__device__ __forceinline__ void mma16816f16(float* c, const uint32_t* a, const uint32_t* b) {
    asm volatile(
        "mma.sync.aligned.m16n8k16.row.col.f32.f16.f16.f32 "
        "{%0,%1,%2,%3}, {%4,%5,%6,%7}, {%8,%9}, {%0,%1,%2,%3};"
        : "+f"(c[0]), "+f"(c[1]), "+f"(c[2]), "+f"(c[3])
        : "r"(a[0]), "r"(a[1]), "r"(a[2]), "r"(a[3]), "r"(b[0]), "r"(b[1]));
}
__device__ __forceinline__ uint32_t pack_f16(float hi, float lo) {
    uint32_t r;
    asm("cvt.rn.f16x2.f32 %0, %1, %2;" : "=r"(r) : "f"(hi), "f"(lo));
    return r;
}

// ---------------------------------------------------------------------------
// merged conversion kernel: x -> fp16 hi/lo; wq/wk/wv/wo -> fp16
// ---------------------------------------------------------------------------
#define N4_X   (T_SEQ * DIM / 4)
#define N4_WQ  (DIM * DIM / 4)
#define N4_WK  (KV_DIM * DIM / 4)
#define N4_WV  (KV_DIM * DIM / 4)
#define N4_WO  (DIM * DIM / 4)
#define N4_TOT (N4_X + N4_WQ + N4_WK + N4_WV + N4_WO)

__global__ __launch_bounds__(256) void cvt_all(
    const float* __restrict__ x,  const float* __restrict__ wq,
    const float* __restrict__ wk, const float* __restrict__ wv,
    const float* __restrict__ wo,
    __half* __restrict__ xh, __half* __restrict__ xl,
    __half* __restrict__ wqh, __half* __restrict__ wkh,
    __half* __restrict__ wvh, __half* __restrict__ woh) {
    int i = blockIdx.x * 256 + threadIdx.x;
    if (i >= N4_TOT) return;
    if (i < N4_X) {
        float4 v = ((const float4*)x)[i];
        __half h0 = __float2half(v.x), h1 = __float2half(v.y);
        __half h2 = __float2half(v.z), h3 = __float2half(v.w);
        ((__half2*)xh)[2 * i]     = __halves2half2(h0, h1);
        ((__half2*)xh)[2 * i + 1] = __halves2half2(h2, h3);
        ((__half2*)xl)[2 * i]     = __halves2half2(
            __float2half(v.x - __half2float(h0)), __float2half(v.y - __half2float(h1)));
        ((__half2*)xl)[2 * i + 1] = __halves2half2(
            __float2half(v.z - __half2float(h2)), __float2half(v.w - __half2float(h3)));
        return;
    }
    const float* src;
    __half* dst;
    int j = i - N4_X;
    if (j < N4_WQ)                          { src = wq; dst = wqh; }
    else if ((j -= N4_WQ) < N4_WK)          { src = wk; dst = wkh; }
    else if ((j -= N4_WK) < N4_WV)          { src = wv; dst = wvh; }
    else { j -= N4_WV;                        src = wo; dst = woh; }
    float4 v = ((const float4*)src)[j];
    ((__half2*)dst)[2 * j]     = __halves2half2(__float2half(v.x), __float2half(v.y));
    ((__half2*)dst)[2 * j + 1] = __halves2half2(__float2half(v.z), __float2half(v.w));
}

// ---------------------------------------------------------------------------
// fp16 2-chain GEMM v4: software-pipelined fragments (LDSM of next k16
// overlaps mma of current k16), 4-stage cp.async ring, ONE sync per chunk
// placed between the two mma bursts. 256 threads, warp tile 32x64, 1 CTA/SM.
//   mode 0: fp32 store (O projection)
//   mode 1: fused QKV epilogue (rope + hi/lo split for Q,K; transpose V)
// ---------------------------------------------------------------------------
#define ROWP 80
#define TILEB (128 * ROWP)        // 10240
#define STAGEB (3 * TILEB)        // 30720 (Ah, Al, Bh)
#define NSTAGE 4
#define EPIPITCH 134
#define GEMM_SMEM (NSTAGE * STAGEB)      // 122880 >= 128*134*4 = 68608
#define GK 4096
#define GNC 128

__global__ __launch_bounds__(256, 1) void gemm_fused(
    const __half* __restrict__ Ah, const __half* __restrict__ Al,
    const __half* __restrict__ B0, const __half* __restrict__ B1,
    const __half* __restrict__ B2,
    float* __restrict__ C, int mode,
    const float* __restrict__ cs, const float* __restrict__ sn,
    const int* __restrict__ spp,
    __half* __restrict__ qbh, __half* __restrict__ qbl,
    __half* __restrict__ kbh, __half* __restrict__ kbl,
    __half* __restrict__ vt) {
    extern __shared__ char smem[];
    const uint32_t sb = smem_u32(smem);
    const int tid = threadIdx.x, warp = tid >> 5, lane = tid & 31;
    const int wm = (warp & 3) << 5;            // 0,32,64,96
    const int wn = (warp >> 2) << 6;           // 0,64
    const int m0 = blockIdx.y << 7;
    const int ntg = blockIdx.x;

    const __half* Bsrc;
    int brow0;
    if (mode == 0)      { Bsrc = B0; brow0 = ntg << 7; }
    else if (ntg < 32)  { Bsrc = B0; brow0 = ntg << 7; }
    else if (ntg < 40)  { Bsrc = B1; brow0 = (ntg - 32) << 7; }
    else                { Bsrc = B2; brow0 = (ntg - 40) << 7; }

    float acc[2][8][4];
    #pragma unroll
    for (int mt = 0; mt < 2; mt++)
        #pragma unroll
        for (int nt = 0; nt < 8; nt++)
            #pragma unroll
            for (int j = 0; j < 4; j++) acc[mt][nt][j] = 0.f;

    auto load_stage = [&](int kofs, int s) {
        const uint32_t base = sb + s * STAGEB;
        #pragma unroll
        for (int t = 0; t < 3; t++) {
            const __half* src = (t == 0) ? Ah : (t == 1) ? Al : Bsrc;
            const int rb = (t < 2) ? m0 : brow0;
            #pragma unroll
            for (int i = 0; i < 2; i++) {
                int idx = tid + (i << 8);
                int r = idx >> 2, c = idx & 3;
                uint32_t d = base + t * TILEB + r * ROWP + (c << 4);
                const void* g = src + (size_t)(rb + r) * GK + kofs + (c << 3);
                CP_ASYNC16(d, g);
            }
        }
    };

    const uint32_t aoffA = (uint32_t)(lane & 15) * ROWP + ((lane >> 4) << 4);
    const uint32_t aoffB = (uint32_t)(((lane >> 4) << 3) + (lane & 7)) * ROWP + (((lane >> 3) & 1) << 4);

    // fragment double buffers (indices constant after inlining/unroll)
    uint32_t ah[2][2][4], al[2][2][4], bh[2][8][2];
    auto ldfrag = [&](int b, uint32_t st, int ks) {
        const uint32_t kb = (uint32_t)ks << 5;
        const uint32_t baseA = st + (uint32_t)wm * ROWP + aoffA + kb;
        const uint32_t baseB = st + 2 * TILEB + (uint32_t)wn * ROWP + aoffB + kb;
        #pragma unroll
        for (int mt = 0; mt < 2; mt++) {
            uint32_t a = baseA + (uint32_t)(mt << 4) * ROWP;
            LDSM_X4(ah[b][mt][0], ah[b][mt][1], ah[b][mt][2], ah[b][mt][3], a);
            LDSM_X4(al[b][mt][0], al[b][mt][1], al[b][mt][2], al[b][mt][3], a + TILEB);
        }
        #pragma unroll
        for (int np = 0; np < 4; np++) {
            uint32_t bb = baseB + (uint32_t)(np << 4) * ROWP;
            LDSM_X4(bh[b][2 * np][0], bh[b][2 * np][1], bh[b][2 * np + 1][0], bh[b][2 * np + 1][1], bb);
        }
    };
    auto mmafrag = [&](int b) {
        #pragma unroll
        for (int nt = 0; nt < 8; nt++)
            #pragma unroll
            for (int mt = 0; mt < 2; mt++) mma16816f16(acc[mt][nt], ah[b][mt], bh[b][nt]);
        #pragma unroll
        for (int nt = 0; nt < 8; nt++)
            #pragma unroll
            for (int mt = 0; mt < 2; mt++) mma16816f16(acc[mt][nt], al[b][mt], bh[b][nt]);
    };

    // prologue: fill the 4-stage ring, then load first fragments
    load_stage(0, 0);   CP_COMMIT();
    load_stage(32, 1);  CP_COMMIT();
    load_stage(64, 2);  CP_COMMIT();
    load_stage(96, 3);  CP_COMMIT();
    CP_WAIT3();
    __syncthreads();
    ldfrag(0, sb, 0);

    for (int c = 0; c < GNC; c++) {
        const int s = c & 3;
        const uint32_t st = sb + s * STAGEB;
        ldfrag(1, st, 1);                 // ks=1 frags — overlaps mma below
        mmafrag(0);                       // ks=0 mma burst
        CP_WAIT2();                       // stage for chunk c+1 arrived
        __syncthreads();                  // all LDSM of stage s done; data c+1 visible
        if (c + 4 < GNC) load_stage((c + 4) << 5, s);
        CP_COMMIT();
        if (c + 1 < GNC) ldfrag(0, sb + ((c + 1) & 3) * STAGEB, 0);  // overlaps mma below
        mmafrag(1);                       // ks=1 mma burst
    }

    const int g4 = lane >> 2, t4 = lane & 3;

    if (mode == 0) {
        #pragma unroll
        for (int mt = 0; mt < 2; mt++) {
            const int row = m0 + wm + (mt << 4) + g4;
            #pragma unroll
            for (int nt = 0; nt < 8; nt++) {
                const int col = (ntg << 7) + wn + (nt << 3) + (t4 << 1);
                *(float2*)&C[(size_t)row * DIM + col]       = make_float2(acc[mt][nt][0], acc[mt][nt][1]);
                *(float2*)&C[(size_t)(row + 8) * DIM + col] = make_float2(acc[mt][nt][2], acc[mt][nt][3]);
            }
        }
        return;
    }

    // ---- mode 1: stage fp32 tile in smem, fused epilogue ----
    __syncthreads();
    float* sf = (float*)smem;
    #pragma unroll
    for (int mt = 0; mt < 2; mt++) {
        const int r0 = wm + (mt << 4) + g4;
        #pragma unroll
        for (int nt = 0; nt < 8; nt++) {
            const int cl = wn + (nt << 3) + (t4 << 1);
            *(float2*)&sf[r0 * EPIPITCH + cl]       = make_float2(acc[mt][nt][0], acc[mt][nt][1]);
            *(float2*)&sf[(r0 + 8) * EPIPITCH + cl] = make_float2(acc[mt][nt][2], acc[mt][nt][3]);
        }
    }
    __syncthreads();

    if (ntg < 40) {
        // Q or K: rope + fp16 hi/lo split; 256 threads = (2 row-halves) x 128 d
        const bool isQ = (ntg < 32);
        const int sp = *spp;
        const int d = tid & 127;
        const int dd = d & 63;
        const bool hi = d >= 64;
        const int r0 = (tid >> 7) << 6;            // 0 or 64
        const float qscale = 0.08838834764831845f;
        __half* dh = isQ ? qbh : kbh;
        __half* dl = isQ ? qbl : kbl;
        const size_t cstride = isQ ? DIM : KV_DIM;
        const size_t cbase = isQ ? (size_t)(ntg << 7) : (size_t)((ntg - 32) << 7);
        for (int r = r0; r < r0 + 64; r++) {
            const int t = m0 + r;
            float cv = cs[(size_t)(sp + t) * 64 + dd];
            float sv = sn[(size_t)(sp + t) * 64 + dd];
            float xa = sf[r * EPIPITCH + d];
            float xb = sf[r * EPIPITCH + (d ^ 64)];
            float yv = hi ? (xa * cv + xb * sv) : (xa * cv - xb * sv);
            if (isQ) yv *= qscale;
            __half hh = __float2half(yv);
            __half ll = __float2half(yv - __half2float(hh));
            size_t e = (size_t)t * cstride + cbase + d;
            dh[e] = hh;
            dl[e] = ll;
        }
    } else {
        // V: transpose + fp16; 256 threads = 128 t x (2 d-halves)
        const int kvh = ntg - 40;
        const int t = tid & 127;
        const int d0 = (tid >> 7) << 6;            // 0 or 64
        #pragma unroll 4
        for (int d = d0; d < d0 + 64; d++) {
            float v = sf[t * EPIPITCH + d];
            vt[(size_t)(kvh * HD + d) * T_SEQ + m0 + t] = __float2half(v);
        }
    }
}

// ---------------------------------------------------------------------------
// Tensor-core causal GQA flash attention (unchanged — proven at 6.9e-4).
// ---------------------------------------------------------------------------
#define BK 64
#define KP 272
#define VP 144
#define KST 17408
#define VOFF 34816
#define STG 53248
#define ATTN_SMEM (2 * STG)

__global__ __launch_bounds__(256, 1) void attn_tc(
    const __half* __restrict__ qbh, const __half* __restrict__ qbl,
    const __half* __restrict__ kbh, const __half* __restrict__ kbl,
    const __half* __restrict__ vt,
    __half* __restrict__ yh, __half* __restrict__ yl) {
    extern __shared__ char smem[];
    const uint32_t sb = smem_u32(smem);
    const int qt = gridDim.x - 1 - blockIdx.x;
    const int h = blockIdx.y, kvh = h >> 2;
    const int tid = threadIdx.x, warp = tid >> 5, lane = tid & 31;
    const int g4 = lane >> 2, t4 = lane & 3;
    const int wr0 = qt * 128 + warp * 16;
    const int ntiles = 2 * qt + 2;

    uint32_t qfh[8][4], qfl[8][4];
    {
        const uint32_t* ph = (const uint32_t*)qbh;
        const uint32_t* pl = (const uint32_t*)qbl;
        #pragma unroll
        for (int ks = 0; ks < 8; ks++)
            #pragma unroll
            for (int j = 0; j < 4; j++) {
                int row = wr0 + g4 + (j & 1) * 8;
                int col = 16 * ks + 2 * t4 + (j >> 1) * 8;
                size_t e = ((size_t)row * DIM + h * HD + col) >> 1;
                qfh[ks][j] = ph[e];
                qfl[ks][j] = pl[e];
            }
    }

    auto load_stage = [&](int kt, int s) {
        const uint32_t base = sb + s * STG;
        const int kbase = kt * BK;
        #pragma unroll
        for (int i = 0; i < 8; i++) {
            int idx = tid + (i << 8);
            int hl = idx >> 10;
            int w = idx & 1023;
            int row = w >> 4, ch = w & 15;
            const __half* src = (hl ? kbl : kbh) + (size_t)(kbase + row) * KV_DIM + kvh * HD + ch * 8;
            CP_ASYNC16(base + hl * KST + row * KP + ch * 16, src);
        }
        #pragma unroll
        for (int i = 0; i < 4; i++) {
            int idx = tid + (i << 8);
            int row = idx >> 3, ch = idx & 7;
            const __half* src = vt + (size_t)(kvh * HD + row) * T_SEQ + kbase + ch * 8;
            CP_ASYNC16(base + VOFF + row * VP + ch * 16, src);
        }
    };

    float O[16][4];
    #pragma unroll
    for (int nt = 0; nt < 16; nt++)
        #pragma unroll
        for (int j = 0; j < 4; j++) O[nt][j] = 0.f;
    float m0 = -1e30f, m1 = -1e30f, l0 = 0.f, l1 = 0.f;

    load_stage(0, 0); CP_COMMIT();
    load_stage(1, 1); CP_COMMIT();

    for (int kt = 0; kt < ntiles; kt++) {
        CP_WAIT1();
        __syncthreads();
        const uint32_t stp = sb + (kt & 1) * STG;
        const int kbase = kt * BK;

        float S[8][4];
        #pragma unroll
        for (int nt = 0; nt < 8; nt++)
            #pragma unroll
            for (int j = 0; j < 4; j++) S[nt][j] = 0.f;
        #pragma unroll
        for (int ks = 0; ks < 8; ks++) {
            #pragma unroll
            for (int nt = 0; nt < 8; nt++) {
                uint32_t a0 = stp + (uint32_t)(nt * 8 + g4) * KP + (16 * ks + 2 * t4) * 2;
                uint32_t bh[2], bl[2];
                LDS32(bh[0], a0);        LDS32(bh[1], a0 + 16);
                LDS32(bl[0], a0 + KST);  LDS32(bl[1], a0 + KST + 16);
                mma16816f16(S[nt], qfh[ks], bh);
                mma16816f16(S[nt], qfl[ks], bh);
                mma16816f16(S[nt], qfh[ks], bl);
            }
        }

        if (kbase + BK - 1 > wr0) {
            #pragma unroll
            for (int nt = 0; nt < 8; nt++) {
                int col = kbase + nt * 8 + 2 * t4;
                int rl = wr0 + g4, rh = wr0 + 8 + g4;
                if (col     > rl) S[nt][0] = -1e30f;
                if (col + 1 > rl) S[nt][1] = -1e30f;
                if (col     > rh) S[nt][2] = -1e30f;
                if (col + 1 > rh) S[nt][3] = -1e30f;
            }
        }

        float mx0 = -1e30f, mx1 = -1e30f;
        #pragma unroll
        for (int nt = 0; nt < 8; nt++) {
            mx0 = fmaxf(mx0, fmaxf(S[nt][0], S[nt][1]));
            mx1 = fmaxf(mx1, fmaxf(S[nt][2], S[nt][3]));
        }
        mx0 = fmaxf(mx0, __shfl_xor_sync(0xffffffffu, mx0, 1));
        mx0 = fmaxf(mx0, __shfl_xor_sync(0xffffffffu, mx0, 2));
        mx1 = fmaxf(mx1, __shfl_xor_sync(0xffffffffu, mx1, 1));
        mx1 = fmaxf(mx1, __shfl_xor_sync(0xffffffffu, mx1, 2));
        float mn0 = fmaxf(m0, mx0), mn1 = fmaxf(m1, mx1);
        float a0 = __expf(m0 - mn0), a1 = __expf(m1 - mn1);
        m0 = mn0; m1 = mn1;
        float ts0 = 0.f, ts1 = 0.f;
        #pragma unroll
        for (int nt = 0; nt < 8; nt++) {
            S[nt][0] = __expf(S[nt][0] - mn0);
            S[nt][1] = __expf(S[nt][1] - mn0);
            S[nt][2] = __expf(S[nt][2] - mn1);
            S[nt][3] = __expf(S[nt][3] - mn1);
            ts0 += S[nt][0] + S[nt][1];
            ts1 += S[nt][2] + S[nt][3];
        }
        ts0 += __shfl_xor_sync(0xffffffffu, ts0, 1);
        ts0 += __shfl_xor_sync(0xffffffffu, ts0, 2);
        ts1 += __shfl_xor_sync(0xffffffffu, ts1, 1);
        ts1 += __shfl_xor_sync(0xffffffffu, ts1, 2);
        l0 = l0 * a0 + ts0;
        l1 = l1 * a1 + ts1;
        #pragma unroll
        for (int nt = 0; nt < 16; nt++) {
            O[nt][0] *= a0; O[nt][1] *= a0;
            O[nt][2] *= a1; O[nt][3] *= a1;
        }

        uint32_t pk[4][4];
        #pragma unroll
        for (int ks = 0; ks < 4; ks++) {
            pk[ks][0] = pack_f16(S[2 * ks][1],     S[2 * ks][0]);
            pk[ks][1] = pack_f16(S[2 * ks][3],     S[2 * ks][2]);
            pk[ks][2] = pack_f16(S[2 * ks + 1][1], S[2 * ks + 1][0]);
            pk[ks][3] = pack_f16(S[2 * ks + 1][3], S[2 * ks + 1][2]);
        }

        #pragma unroll
        for (int ks = 0; ks < 4; ks++) {
            #pragma unroll
            for (int nt = 0; nt < 16; nt++) {
                uint32_t a0 = stp + VOFF + (uint32_t)(nt * 8 + g4) * VP + (16 * ks + 2 * t4) * 2;
                uint32_t b[2];
                LDS32(b[0], a0);
                LDS32(b[1], a0 + 16);
                mma16816f16(O[nt], pk[ks], b);
            }
        }

        __syncthreads();
        if (kt + 2 < ntiles) load_stage(kt + 2, kt & 1);
        CP_COMMIT();
    }

    float i0 = 1.f / l0, i1 = 1.f / l1;
    #pragma unroll
    for (int nt = 0; nt < 16; nt++) {
        int col = h * HD + nt * 8 + 2 * t4;
        size_t e0 = (size_t)(wr0 + g4) * DIM + col;
        size_t e1 = (size_t)(wr0 + 8 + g4) * DIM + col;
        float v00 = O[nt][0] * i0, v01 = O[nt][1] * i0;
        float v10 = O[nt][2] * i1, v11 = O[nt][3] * i1;
        __half h00 = __float2half(v00), h01 = __float2half(v01);
        __half h10 = __float2half(v10), h11 = __float2half(v11);
        *(__half2*)(yh + e0) = __halves2half2(h00, h01);
        *(__half2*)(yh + e1) = __halves2half2(h10, h11);
        *(__half2*)(yl + e0) = __halves2half2(
            __float2half(v00 - __half2float(h00)), __float2half(v01 - __half2float(h01)));
        *(__half2*)(yl + e1) = __halves2half2(
            __float2half(v10 - __half2float(h10)), __float2half(v11 - __half2float(h11)));
    }
}

// ---------------------------------------------------------------------------
extern "C" void kernel_launch(void* const* d_in, const int* in_sizes, int n_in,
                              void* d_out, int out_size) {
    const float* x  = (const float*)d_in[0];
    const float* cs = (const float*)d_in[1];
    const float* sn = (const float*)d_in[2];
    const float* wq = (const float*)d_in[3];
    const float* wk = (const float*)d_in[4];
    const float* wv = (const float*)d_in[5];
    const float* wo = (const float*)d_in[6];
    const int*   sp = (const int*)d_in[7];
    float* out = (float*)d_out;

    __half *xh, *xl, *yh, *yl, *wqh, *wkh, *wvh, *woh;
    __half *qbh, *qbl, *kbh, *kbl, *vt;
    cudaGetSymbolAddress((void**)&xh, g_xh);   cudaGetSymbolAddress((void**)&xl, g_xl);
    cudaGetSymbolAddress((void**)&yh, g_yh);   cudaGetSymbolAddress((void**)&yl, g_yl);
    cudaGetSymbolAddress((void**)&wqh, g_wqh); cudaGetSymbolAddress((void**)&wkh, g_wkh);
    cudaGetSymbolAddress((void**)&wvh, g_wvh); cudaGetSymbolAddress((void**)&woh, g_woh);
    cudaGetSymbolAddress((void**)&qbh, g_qbh); cudaGetSymbolAddress((void**)&qbl, g_qbl);
    cudaGetSymbolAddress((void**)&kbh, g_kbh); cudaGetSymbolAddress((void**)&kbl, g_kbl);
    cudaGetSymbolAddress((void**)&vt, g_vt);

    cudaFuncSetAttribute(gemm_fused, cudaFuncAttributeMaxDynamicSharedMemorySize, GEMM_SMEM);
    cudaFuncSetAttribute(attn_tc, cudaFuncAttributeMaxDynamicSharedMemorySize, ATTN_SMEM);

    cvt_all<<<(N4_TOT + 255) / 256, 256>>>(x, wq, wk, wv, wo,
                                           xh, xl, wqh, wkh, wvh, woh);
    gemm_fused<<<dim3(48, T_SEQ / 128), 256, GEMM_SMEM>>>(
        xh, xl, wqh, wkh, wvh, nullptr, 1,
        cs, sn, sp, qbh, qbl, kbh, kbl, vt);
    attn_tc<<<dim3(T_SEQ / 128, NH), 256, ATTN_SMEM>>>(qbh, qbl, kbh, kbl, vt, yh, yl);
    gemm_fused<<<dim3(32, T_SEQ / 128), 256, GEMM_SMEM>>>(
        yh, yl, woh, nullptr, nullptr, out, 0,
        nullptr, nullptr, nullptr, nullptr, nullptr, nullptr, nullptr, nullptr);
}